// round 1
// baseline (speedup 1.0000x reference)
#include <cuda_runtime.h>
#include <cuda_bf16.h>
#include <cstdint>

// Problem constants
#define BB 4
#define SS 1024
#define DD 1024
#define HH 16
#define DH 64

// Scratch (device globals; no allocation at runtime)
__device__ float gQ1[BB*HH*SS*DH];
__device__ float gQ2[BB*HH*SS*DH];
__device__ float gK1[BB*HH*SS*DH];
__device__ float gK2[BB*HH*SS*DH];
__device__ float gV [BB*HH*SS*DH];
__device__ float gCtx[BB*SS*DD];
__device__ float gScaleArr[BB*DD];
__device__ float gBiasArr [BB*DD];

// ---------------------------------------------------------------------------
// Kernel A: QKV projection GEMM.
// C[m][n] = X[m][:] . W[n][:] + bias[n],  M=4096, N=5120, K=1024
// n in [0,1024)->q1, [1024,2048)->q2, [2048,3072)->k1, [3072,4096)->k2, [4096,5120)->v
// Scatter into per-head layout [B][H][S][DH].
// ---------------------------------------------------------------------------
__global__ __launch_bounds__(256, 2)
void qkv_gemm(const float* __restrict__ X,
              const float* __restrict__ wq, const float* __restrict__ wqb,
              const float* __restrict__ wk, const float* __restrict__ wkb,
              const float* __restrict__ wv, const float* __restrict__ wvb)
{
    __shared__ float As[16][128];
    __shared__ float Bs[16][128];

    const int n0 = blockIdx.x * 128;
    const int m0 = blockIdx.y * 128;

    const float* W;
    const float* Wb;
    if (n0 < 2048)      { W = wq + (size_t)n0 * 1024;          Wb = wqb + n0; }
    else if (n0 < 4096) { W = wk + (size_t)(n0 - 2048) * 1024; Wb = wkb + (n0 - 2048); }
    else                { W = wv + (size_t)(n0 - 4096) * 1024; Wb = wvb + (n0 - 4096); }

    const int tid = threadIdx.x;
    const int tx = tid & 15;
    const int ty = tid >> 4;

    float acc[8][8];
#pragma unroll
    for (int i = 0; i < 8; i++)
#pragma unroll
        for (int j = 0; j < 8; j++) acc[i][j] = 0.f;

    for (int k0 = 0; k0 < 1024; k0 += 16) {
#pragma unroll
        for (int r = 0; r < 2; r++) {
            int idx = tid + r * 256;
            int row = idx >> 2;
            int kq  = idx & 3;
            float4 a = *(const float4*)&X[(size_t)(m0 + row) * 1024 + k0 + kq * 4];
            As[kq*4+0][row] = a.x; As[kq*4+1][row] = a.y;
            As[kq*4+2][row] = a.z; As[kq*4+3][row] = a.w;
            float4 w = *(const float4*)&W[(size_t)row * 1024 + k0 + kq * 4];
            Bs[kq*4+0][row] = w.x; Bs[kq*4+1][row] = w.y;
            Bs[kq*4+2][row] = w.z; Bs[kq*4+3][row] = w.w;
        }
        __syncthreads();
#pragma unroll
        for (int kk = 0; kk < 16; kk++) {
            float a[8], bv[8];
            *(float4*)&a[0]  = *(float4*)&As[kk][ty*8];
            *(float4*)&a[4]  = *(float4*)&As[kk][ty*8+4];
            *(float4*)&bv[0] = *(float4*)&Bs[kk][tx*8];
            *(float4*)&bv[4] = *(float4*)&Bs[kk][tx*8+4];
#pragma unroll
            for (int i = 0; i < 8; i++)
#pragma unroll
                for (int j = 0; j < 8; j++)
                    acc[i][j] += a[i] * bv[j];
        }
        __syncthreads();
    }

    // Epilogue: add bias, scatter to per-head buffers.
#pragma unroll
    for (int i = 0; i < 8; i++) {
        int m = m0 + ty * 8 + i;
        int b = m >> 10;
        int s = m & 1023;
#pragma unroll
        for (int j = 0; j < 8; j++) {
            int n = n0 + tx * 8 + j;
            float val = acc[i][j] + Wb[tx * 8 + j];
            int sect = n >> 10;
            int loc  = n & 1023;
            int h    = loc >> 6;
            int dh   = loc & 63;
            float* dst = (sect == 0) ? gQ1 : (sect == 1) ? gQ2 :
                         (sect == 2) ? gK1 : (sect == 3) ? gK2 : gV;
            dst[((size_t)((b << 4) + h) * 1024 + s) * 64 + dh] = val;
        }
    }
}

// ---------------------------------------------------------------------------
// Kernel B: dual attention per (b, h, 16-query tile).
// smem layout (floats): S1[16*1024] | S2[16*1024] | KT[16*1028] | QS[2*16*64]
// ---------------------------------------------------------------------------
#define KT_STRIDE 1028
#define SMEM_FLOATS (16384 + 16384 + 16448 + 2048)

__global__ __launch_bounds__(256, 1)
void attn_kernel(const float* __restrict__ Cmask,
                 const int*   __restrict__ pad,
                 const float* __restrict__ lamp,
                 float* __restrict__ attn1,
                 float* __restrict__ attn2)
{
    extern __shared__ float sm[];
    float* S1 = sm;
    float* S2 = sm + 16384;
    float* KT = sm + 32768;            // 16 rows x stride 1028
    float* QS = sm + 32768 + 16448;    // [2][16][64]

    const int qt = blockIdx.x;
    const int h  = blockIdx.y;
    const int b  = blockIdx.z;
    const int tid = threadIdx.x;
    const int bh = b * 16 + h;
    const int qbase = qt * 16;

    // Load Q tiles (both variants)
    for (int t = tid; t < 1024; t += 256) {
        int qq = t >> 6, d = t & 63;
        QS[t]        = gQ1[((size_t)bh * 1024 + qbase + qq) * 64 + d];
        QS[1024 + t] = gQ2[((size_t)bh * 1024 + qbase + qq) * 64 + d];
    }

    const int ty = tid >> 7;    // 0..1  (query rows ty*8..ty*8+8)
    const int tx = tid & 127;   // keys tx*8..tx*8+8
    const float lam = lamp[0];

    // ---- Phase 1: scores for each variant ----
    for (int var = 0; var < 2; var++) {
        const float* Kg = var ? gK2 : gK1;
        const float* Qv = QS + var * 1024;
        float acc[8][8];
#pragma unroll
        for (int i = 0; i < 8; i++)
#pragma unroll
            for (int j = 0; j < 8; j++) acc[i][j] = 0.f;

        for (int dc = 0; dc < 4; dc++) {
            __syncthreads();   // KT safe to overwrite
            for (int t = tid; t < 4096; t += 256) {
                int kk = t >> 2, dq = t & 3;
                float4 v = *(const float4*)&Kg[((size_t)bh * 1024 + kk) * 64 + dc * 16 + dq * 4];
                KT[(dq*4+0)*KT_STRIDE + kk] = v.x;
                KT[(dq*4+1)*KT_STRIDE + kk] = v.y;
                KT[(dq*4+2)*KT_STRIDE + kk] = v.z;
                KT[(dq*4+3)*KT_STRIDE + kk] = v.w;
            }
            __syncthreads();
#pragma unroll
            for (int dd = 0; dd < 16; dd++) {
                float qv[8];
#pragma unroll
                for (int i = 0; i < 8; i++) qv[i] = Qv[(ty*8+i)*64 + dc*16 + dd];
                float kv[8];
                *(float4*)&kv[0] = *(float4*)&KT[dd*KT_STRIDE + tx*8];
                *(float4*)&kv[4] = *(float4*)&KT[dd*KT_STRIDE + tx*8 + 4];
#pragma unroll
                for (int i = 0; i < 8; i++)
#pragma unroll
                    for (int j = 0; j < 8; j++)
                        acc[i][j] += qv[i] * kv[j];
            }
        }
        float* Sv = var ? S2 : S1;
#pragma unroll
        for (int j = 0; j < 8; j++) {
            int k = tx * 8 + j;
            bool masked = (pad[b * 1024 + k] == 0);
#pragma unroll
            for (int i = 0; i < 8; i++) {
                float v = acc[i][j] * 0.125f;
                Sv[(ty*8+i)*1024 + k] = masked ? -1e9f : v;
            }
        }
        __syncthreads();
    }

    // ---- Softmax (32 row-tasks over 8 warps), write attn out + normalize in smem ----
    {
        const int warp = tid >> 5, lane = tid & 31;
        for (int task = warp; task < 32; task += 8) {
            int var = task >> 4;
            int q   = task & 15;
            float* row = (var ? S2 : S1) + q * 1024;
            float vreg[32];
            float m = -3.4e38f;
#pragma unroll
            for (int j = 0; j < 32; j++) { vreg[j] = row[lane + 32*j]; m = fmaxf(m, vreg[j]); }
#pragma unroll
            for (int o = 16; o > 0; o >>= 1) m = fmaxf(m, __shfl_xor_sync(0xffffffffu, m, o));
            float s = 0.f;
#pragma unroll
            for (int j = 0; j < 32; j++) { vreg[j] = __expf(vreg[j] - m); s += vreg[j]; }
#pragma unroll
            for (int o = 16; o > 0; o >>= 1) s += __shfl_xor_sync(0xffffffffu, s, o);
            float r = 1.0f / s;
            float* gout = (var ? attn2 : attn1) + ((size_t)bh * 1024 + qbase + q) * 1024;
#pragma unroll
            for (int j = 0; j < 32; j++) {
                float e = vreg[j] * r;
                row[lane + 32*j]  = e;
                gout[lane + 32*j] = e;
            }
        }
    }
    __syncthreads();

    // ---- Combine: S1 <- C * (attn1 - lam * attn2) ----
    for (int t = tid; t < 16384; t += 256) {
        int q = t >> 10, k = t & 1023;
        float c = Cmask[((size_t)b * 1024 + qbase + q) * 1024 + k];
        S1[t] = c * (S1[t] - lam * S2[t]);
    }
    __syncthreads();

    // ---- Phase 2: ctx[16][64] = combined[16][1024] @ V[1024][64] ----
    {
        const int pos = tid & 31;
        const int ks  = tid >> 5;      // 0..7 (k-split inside each 128-chunk)
        const int qg  = pos >> 3;      // 0..3 -> 4 query rows
        const int dgp = pos & 7;       // 0..7 -> 8 d cols
        float acc2[4][8];
#pragma unroll
        for (int i = 0; i < 4; i++)
#pragma unroll
            for (int j = 0; j < 8; j++) acc2[i][j] = 0.f;

        float* VT = KT;   // reuse, [128][68]
        for (int ch = 0; ch < 8; ch++) {
            __syncthreads();
            for (int t = tid; t < 2048; t += 256) {
                int kk = t >> 4, dq = t & 15;
                float4 v = *(const float4*)&gV[((size_t)bh * 1024 + ch * 128 + kk) * 64 + dq * 4];
                *(float4*)&VT[kk * 68 + dq * 4] = v;
            }
            __syncthreads();
            int klo = ks * 16;
#pragma unroll 4
            for (int k = klo; k < klo + 16; k++) {
                float cb[4];
#pragma unroll
                for (int i = 0; i < 4; i++) cb[i] = S1[(qg*4+i)*1024 + ch*128 + k];
                float vv[8];
                *(float4*)&vv[0] = *(float4*)&VT[k*68 + dgp*8];
                *(float4*)&vv[4] = *(float4*)&VT[k*68 + dgp*8 + 4];
#pragma unroll
                for (int i = 0; i < 4; i++)
#pragma unroll
                    for (int j = 0; j < 8; j++)
                        acc2[i][j] += cb[i] * vv[j];
            }
        }
        __syncthreads();
        // partials -> S2 (free now)
#pragma unroll
        for (int i = 0; i < 4; i++)
#pragma unroll
            for (int j = 0; j < 8; j++)
                S2[(ks*16 + qg*4 + i) * 64 + dgp*8 + j] = acc2[i][j];
        __syncthreads();
        for (int t = tid; t < 1024; t += 256) {
            int q = t >> 6, d = t & 63;
            float ssum = 0.f;
#pragma unroll
            for (int k2 = 0; k2 < 8; k2++) ssum += S2[(k2*16 + q) * 64 + d];
            gCtx[((size_t)b * 1024 + qbase + q) * 1024 + h * 64 + d] = ssum;
        }
    }
}

// ---------------------------------------------------------------------------
// Kernel C1: per (b,h) GroupNorm stats -> folded per-(b,d) scale/bias
// scaled = ((x - mean) * rstd * gn_w + gn_b) * (1 - 0.8)
// ---------------------------------------------------------------------------
__global__ void stats_kernel(const float* __restrict__ gnw,
                             const float* __restrict__ gnb)
{
    const int bh = blockIdx.x;
    const int b = bh >> 4, h = bh & 15;
    const int tid = threadIdx.x;
    __shared__ float rs[256], rq[256];
    float s = 0.f, sq = 0.f;
    for (int t = tid; t < 65536; t += 256) {
        int srow = t >> 6, d = t & 63;
        float x = gCtx[((size_t)b * 1024 + srow) * 1024 + h * 64 + d];
        s += x; sq += x * x;
    }
    rs[tid] = s; rq[tid] = sq;
    __syncthreads();
    for (int o = 128; o > 0; o >>= 1) {
        if (tid < o) { rs[tid] += rs[tid + o]; rq[tid] += rq[tid + o]; }
        __syncthreads();
    }
    if (tid < 64) {
        float mean = rs[0] * (1.0f / 65536.0f);
        float var  = rq[0] * (1.0f / 65536.0f) - mean * mean;
        float rstd = rsqrtf(var + 1e-5f);
        int d = h * 64 + tid;
        float w = gnw[d];
        float scl = rstd * w * 0.19999999999999996f;
        gScaleArr[b * 1024 + d] = scl;
        gBiasArr [b * 1024 + d] = (gnb[d] - mean * rstd * w) * 0.19999999999999996f;
    }
}

// ---------------------------------------------------------------------------
// Kernel C2: output GEMM. out[m][n] = (ctx[m][:]*scale[b][:]+bias[b][:]) . Wo[n][:] + ob[n]
// M=4096, N=1024, K=1024
// ---------------------------------------------------------------------------
__global__ __launch_bounds__(256, 2)
void out_gemm(const float* __restrict__ Wo,
              const float* __restrict__ ob,
              float* __restrict__ out)
{
    __shared__ float As[16][128];
    __shared__ float Bs[16][128];

    const int n0 = blockIdx.x * 128;
    const int m0 = blockIdx.y * 128;
    const int bb = m0 >> 10;   // batch (tiles never straddle batch boundary)

    const int tid = threadIdx.x;
    const int tx = tid & 15;
    const int ty = tid >> 4;

    float acc[8][8];
#pragma unroll
    for (int i = 0; i < 8; i++)
#pragma unroll
        for (int j = 0; j < 8; j++) acc[i][j] = 0.f;

    for (int k0 = 0; k0 < 1024; k0 += 16) {
#pragma unroll
        for (int r = 0; r < 2; r++) {
            int idx = tid + r * 256;
            int row = idx >> 2;
            int kq  = idx & 3;
            float4 a  = *(const float4*)&gCtx[(size_t)(m0 + row) * 1024 + k0 + kq * 4];
            float4 sc = *(const float4*)&gScaleArr[bb * 1024 + k0 + kq * 4];
            float4 bi = *(const float4*)&gBiasArr [bb * 1024 + k0 + kq * 4];
            As[kq*4+0][row] = a.x * sc.x + bi.x;
            As[kq*4+1][row] = a.y * sc.y + bi.y;
            As[kq*4+2][row] = a.z * sc.z + bi.z;
            As[kq*4+3][row] = a.w * sc.w + bi.w;
            float4 w = *(const float4*)&Wo[(size_t)(n0 + row) * 1024 + k0 + kq * 4];
            Bs[kq*4+0][row] = w.x; Bs[kq*4+1][row] = w.y;
            Bs[kq*4+2][row] = w.z; Bs[kq*4+3][row] = w.w;
        }
        __syncthreads();
#pragma unroll
        for (int kk = 0; kk < 16; kk++) {
            float a[8], bv[8];
            *(float4*)&a[0]  = *(float4*)&As[kk][ty*8];
            *(float4*)&a[4]  = *(float4*)&As[kk][ty*8+4];
            *(float4*)&bv[0] = *(float4*)&Bs[kk][tx*8];
            *(float4*)&bv[4] = *(float4*)&Bs[kk][tx*8+4];
#pragma unroll
            for (int i = 0; i < 8; i++)
#pragma unroll
                for (int j = 0; j < 8; j++)
                    acc[i][j] += a[i] * bv[j];
        }
        __syncthreads();
    }

#pragma unroll
    for (int i = 0; i < 8; i++) {
        int m = m0 + ty * 8 + i;
#pragma unroll
        for (int j = 0; j < 8; j++) {
            int n = n0 + tx * 8 + j;
            out[(size_t)m * 1024 + n] = acc[i][j] + ob[n];
        }
    }
}

// ---------------------------------------------------------------------------
// Launch
// ---------------------------------------------------------------------------
extern "C" void kernel_launch(void* const* d_in, const int* in_sizes, int n_in,
                              void* d_out, int out_size)
{
    const float* x    = (const float*)d_in[0];
    const float* lam  = (const float*)d_in[1];
    const float* C    = (const float*)d_in[2];
    const int*   pad  = (const int*)  d_in[3];
    const float* wq   = (const float*)d_in[4];
    const float* wqb  = (const float*)d_in[5];
    const float* wk   = (const float*)d_in[6];
    const float* wkb  = (const float*)d_in[7];
    const float* wv   = (const float*)d_in[8];
    const float* wvb  = (const float*)d_in[9];
    const float* wo   = (const float*)d_in[10];
    const float* wob  = (const float*)d_in[11];
    const float* gnw  = (const float*)d_in[12];
    const float* gnb  = (const float*)d_in[13];

    float* out   = (float*)d_out;
    float* attn1 = out + (size_t)BB * SS * DD;                    // 4,194,304
    float* attn2 = attn1 + (size_t)BB * HH * SS * SS;             // +67,108,864

    cudaFuncSetAttribute(attn_kernel, cudaFuncAttributeMaxDynamicSharedMemorySize,
                         SMEM_FLOATS * (int)sizeof(float));

    qkv_gemm<<<dim3(40, 32), 256>>>(x, wq, wqb, wk, wkb, wv, wvb);
    attn_kernel<<<dim3(64, 16, 4), 256, SMEM_FLOATS * sizeof(float)>>>(C, pad, lam, attn1, attn2);
    stats_kernel<<<64, 256>>>(gnw, gnb);
    out_gemm<<<dim3(8, 32), 256>>>(wo, wob, out);
}

// round 3
// speedup vs baseline: 1.3492x; 1.3492x over previous
#include <cuda_runtime.h>
#include <cuda_bf16.h>
#include <cstdint>

// Problem constants
#define BB 4
#define SS 1024
#define DD 1024
#define HH 16
#define DH 64

// Scratch (device globals; no allocation at runtime)
__device__ float gQ1[BB*HH*SS*DH];
__device__ float gQ2[BB*HH*SS*DH];
__device__ float gK1[BB*HH*SS*DH];
__device__ float gK2[BB*HH*SS*DH];
__device__ float gV [BB*HH*SS*DH];
__device__ float gCtx[BB*SS*DD];
__device__ float gScaleArr[BB*DD];
__device__ float gBiasArr [BB*DD];

// ===========================================================================
// mma.sync helpers (base PTX, assembles for sm_103)
// ===========================================================================
static __device__ __forceinline__ uint32_t smem_u32(const void* p) {
    uint32_t a;
    asm("{ .reg .u64 t; cvta.to.shared.u64 t, %1; cvt.u32.u64 %0, t; }"
        : "=r"(a) : "l"(p));
    return a;
}

static __device__ __forceinline__ void ldm_x4(uint32_t* r, uint32_t addr) {
    asm volatile("ldmatrix.sync.aligned.m8n8.x4.shared.b16 {%0,%1,%2,%3}, [%4];"
                 : "=r"(r[0]), "=r"(r[1]), "=r"(r[2]), "=r"(r[3]) : "r"(addr));
}

static __device__ __forceinline__ void mma16816(float* c, const uint32_t* a,
                                                const uint32_t* b) {
    asm volatile(
        "mma.sync.aligned.m16n8k16.row.col.f32.bf16.bf16.f32 "
        "{%0,%1,%2,%3}, {%4,%5,%6,%7}, {%8,%9}, {%0,%1,%2,%3};"
        : "+f"(c[0]), "+f"(c[1]), "+f"(c[2]), "+f"(c[3])
        : "r"(a[0]), "r"(a[1]), "r"(a[2]), "r"(a[3]), "r"(b[0]), "r"(b[1]));
}

// split fp32 float4 -> hi/lo bf16 uint2 pair
static __device__ __forceinline__ void split4(float4 v, uint2& hv, uint2& lv) {
    __nv_bfloat16 h0 = __float2bfloat16(v.x);
    __nv_bfloat16 h1 = __float2bfloat16(v.y);
    __nv_bfloat16 h2 = __float2bfloat16(v.z);
    __nv_bfloat16 h3 = __float2bfloat16(v.w);
    __nv_bfloat16 l0 = __float2bfloat16(v.x - __bfloat162float(h0));
    __nv_bfloat16 l1 = __float2bfloat16(v.y - __bfloat162float(h1));
    __nv_bfloat16 l2 = __float2bfloat16(v.z - __bfloat162float(h2));
    __nv_bfloat16 l3 = __float2bfloat16(v.w - __bfloat162float(h3));
    __nv_bfloat162 hp0; hp0.x = h0; hp0.y = h1;
    __nv_bfloat162 hp1; hp1.x = h2; hp1.y = h3;
    __nv_bfloat162 lp0; lp0.x = l0; lp0.y = l1;
    __nv_bfloat162 lp1; lp1.x = l2; lp1.y = l3;
    hv = make_uint2(*reinterpret_cast<uint32_t*>(&hp0),
                    *reinterpret_cast<uint32_t*>(&hp1));
    lv = make_uint2(*reinterpret_cast<uint32_t*>(&lp0),
                    *reinterpret_cast<uint32_t*>(&lp1));
}

// smem tile byte offset with ldmatrix-friendly swizzle.
// tile: rows x 32 bf16 (64B/row = 4 x 16B chunks), chunk ^= (row>>1)&3
static __device__ __forceinline__ uint32_t sw_off(int row, int chunk) {
    return (uint32_t)(row * 64 + ((chunk ^ ((row >> 1) & 3)) << 4));
}

// ===========================================================================
// mma_gemm<MODE>: C[m0:+128, n0:+128] = A @ W^T + bias, K=1024, split-bf16.
// MODE 0: A = X; W/bias = qkv sections; scatter to per-head fp32 buffers.
// MODE 1: A = gCtx folded with gScaleArr/gBiasArr; W = Wo; writes out.
// ===========================================================================
template<int MODE>
__global__ __launch_bounds__(256, 2)
void mma_gemm(const float* __restrict__ Ain,
              const float* __restrict__ wq, const float* __restrict__ wqb,
              const float* __restrict__ wk, const float* __restrict__ wkb,
              const float* __restrict__ wv, const float* __restrict__ wvb,
              const float* __restrict__ Wo, const float* __restrict__ ob,
              float* __restrict__ out)
{
    __shared__ __align__(16) char sm[32768];
    char* Ahi = sm;
    char* Alo = sm + 8192;
    char* Bhi = sm + 16384;
    char* Blo = sm + 24576;

    const int tid  = threadIdx.x;
    const int lane = tid & 31;
    const int warp = tid >> 5;
    const int wm   = warp >> 1;   // 0..3
    const int wn   = warp & 1;    // 0..1
    const int n0 = blockIdx.x * 128;
    const int m0 = blockIdx.y * 128;
    const int b  = m0 >> 10;

    const float* A = (MODE == 0) ? Ain : gCtx;
    const float* W;
    const float* Wb;
    if (MODE == 0) {
        if (n0 < 2048)      { W = wq + (size_t)n0 * 1024;          Wb = wqb + n0; }
        else if (n0 < 4096) { W = wk + (size_t)(n0 - 2048) * 1024; Wb = wkb + (n0 - 2048); }
        else                { W = wv + (size_t)(n0 - 4096) * 1024; Wb = wvb + (n0 - 4096); }
    } else {
        W = Wo + (size_t)n0 * 1024; Wb = ob + n0;
    }

    const uint32_t AhiU = smem_u32(Ahi), AloU = smem_u32(Alo);
    const uint32_t BhiU = smem_u32(Bhi), BloU = smem_u32(Blo);

    float acc[2][8][4];
#pragma unroll
    for (int i = 0; i < 2; i++)
#pragma unroll
        for (int j = 0; j < 8; j++)
#pragma unroll
            for (int v = 0; v < 4; v++) acc[i][j][v] = 0.f;

    const int ldrow = tid >> 1;          // 0..127
    const int ldf4b = (tid & 1) * 4;     // 0 or 4 (f4 index base)

    for (int c = 0; c < 32; c++) {
        const int k0 = c * 32;
        // ---- A tile 128x32 fp32 -> hi/lo bf16 ----
        {
            const float* src = A + (size_t)(m0 + ldrow) * 1024 + k0 + ldf4b * 4;
#pragma unroll
            for (int i = 0; i < 4; i++) {
                float4 v = *(const float4*)(src + i * 4);
                if (MODE == 1) {
                    int kc = k0 + ldf4b * 4 + i * 4;
                    float4 sc = *(const float4*)&gScaleArr[b * 1024 + kc];
                    float4 bi = *(const float4*)&gBiasArr [b * 1024 + kc];
                    v.x = v.x * sc.x + bi.x; v.y = v.y * sc.y + bi.y;
                    v.z = v.z * sc.z + bi.z; v.w = v.w * sc.w + bi.w;
                }
                uint2 hv, lv;
                split4(v, hv, lv);
                int f4 = ldf4b + i;
                uint32_t off = sw_off(ldrow, f4 >> 1) + (f4 & 1) * 8;
                *(uint2*)(Ahi + off) = hv;
                *(uint2*)(Alo + off) = lv;
            }
        }
        // ---- B tile 128x32 fp32 -> hi/lo bf16 ----
        {
            const float* src = W + (size_t)ldrow * 1024 + k0 + ldf4b * 4;
#pragma unroll
            for (int i = 0; i < 4; i++) {
                float4 v = *(const float4*)(src + i * 4);
                uint2 hv, lv;
                split4(v, hv, lv);
                int f4 = ldf4b + i;
                uint32_t off = sw_off(ldrow, f4 >> 1) + (f4 & 1) * 8;
                *(uint2*)(Bhi + off) = hv;
                *(uint2*)(Blo + off) = lv;
            }
        }
        __syncthreads();

#pragma unroll
        for (int kk = 0; kk < 2; kk++) {
            // A fragments: rows wm*32 + mi*16 (+ lane mapping), k16 = kk
            uint32_t ah[2][4], al[2][4];
            const int arow = wm * 32 + (lane & 7) + (((lane >> 3) & 1) << 3);
            const int achunk = kk * 2 + (lane >> 4);
#pragma unroll
            for (int mi = 0; mi < 2; mi++) {
                uint32_t off = sw_off(arow + mi * 16, achunk);
                ldm_x4(ah[mi], AhiU + off);
                ldm_x4(al[mi], AloU + off);
            }
            const int brow0 = wn * 64 + (lane & 7) + ((lane >> 4) << 3);
            const int bchunk = kk * 2 + ((lane >> 3) & 1);
#pragma unroll
            for (int half = 0; half < 2; half++) {
                uint32_t bh[2][4], bl[2][4];
#pragma unroll
                for (int j = 0; j < 2; j++) {
                    uint32_t off = sw_off(brow0 + half * 32 + j * 16, bchunk);
                    ldm_x4(bh[j], BhiU + off);
                    ldm_x4(bl[j], BloU + off);
                }
#pragma unroll
                for (int mi = 0; mi < 2; mi++)
#pragma unroll
                    for (int j = 0; j < 2; j++)
#pragma unroll
                        for (int s = 0; s < 2; s++) {
                            float* cp = acc[mi][half * 4 + j * 2 + s];
                            mma16816(cp, ah[mi], &bh[j][s * 2]);
                            mma16816(cp, ah[mi], &bl[j][s * 2]);
                            mma16816(cp, al[mi], &bh[j][s * 2]);
                        }
            }
        }
        __syncthreads();
    }

    // ---- epilogue ----
    if (MODE == 0) {
        const int sect = n0 >> 10;
        float* dst = (sect == 0) ? gQ1 : (sect == 1) ? gQ2 :
                     (sect == 2) ? gK1 : (sect == 3) ? gK2 : gV;
#pragma unroll
        for (int mi = 0; mi < 2; mi++) {
            int m = m0 + wm * 32 + mi * 16 + (lane >> 2);
            int s = m & 1023;
#pragma unroll
            for (int nh = 0; nh < 8; nh++) {
                int nl = wn * 64 + nh * 8 + 2 * (lane & 3);
                int nn = (n0 & 1023) + nl;
                int h = nn >> 6, dh = nn & 63;
                float b0 = Wb[nl], b1 = Wb[nl + 1];
                size_t base = ((size_t)((b << 4) + h) * 1024 + s) * 64 + dh;
                float2 v0; v0.x = acc[mi][nh][0] + b0; v0.y = acc[mi][nh][1] + b1;
                float2 v1; v1.x = acc[mi][nh][2] + b0; v1.y = acc[mi][nh][3] + b1;
                *(float2*)&dst[base]          = v0;
                *(float2*)&dst[base + 8 * 64] = v1;
            }
        }
    } else {
#pragma unroll
        for (int mi = 0; mi < 2; mi++) {
            int m = m0 + wm * 32 + mi * 16 + (lane >> 2);
#pragma unroll
            for (int nh = 0; nh < 8; nh++) {
                int nl = wn * 64 + nh * 8 + 2 * (lane & 3);
                float b0 = Wb[nl], b1 = Wb[nl + 1];
                float2 v0; v0.x = acc[mi][nh][0] + b0; v0.y = acc[mi][nh][1] + b1;
                float2 v1; v1.x = acc[mi][nh][2] + b0; v1.y = acc[mi][nh][3] + b1;
                *(float2*)&out[(size_t)m * 1024 + n0 + nl]       = v0;
                *(float2*)&out[(size_t)(m + 8) * 1024 + n0 + nl] = v1;
            }
        }
    }
}

// ---------------------------------------------------------------------------
// Kernel B: dual attention per (b, h, 16-query tile).  (fp32, as round 1)
// ---------------------------------------------------------------------------
#define KT_STRIDE 1028
#define SMEM_FLOATS (16384 + 16384 + 16448 + 2048)

__global__ __launch_bounds__(256, 1)
void attn_kernel(const float* __restrict__ Cmask,
                 const int*   __restrict__ pad,
                 const float* __restrict__ lamp,
                 float* __restrict__ attn1,
                 float* __restrict__ attn2)
{
    extern __shared__ float sm[];
    float* S1 = sm;
    float* S2 = sm + 16384;
    float* KT = sm + 32768;
    float* QS = sm + 32768 + 16448;

    const int qt = blockIdx.x;
    const int h  = blockIdx.y;
    const int b  = blockIdx.z;
    const int tid = threadIdx.x;
    const int bh = b * 16 + h;
    const int qbase = qt * 16;

    for (int t = tid; t < 1024; t += 256) {
        int qq = t >> 6, d = t & 63;
        QS[t]        = gQ1[((size_t)bh * 1024 + qbase + qq) * 64 + d];
        QS[1024 + t] = gQ2[((size_t)bh * 1024 + qbase + qq) * 64 + d];
    }

    const int ty = tid >> 7;
    const int tx = tid & 127;
    const float lam = lamp[0];

    for (int var = 0; var < 2; var++) {
        const float* Kg = var ? gK2 : gK1;
        const float* Qv = QS + var * 1024;
        float acc[8][8];
#pragma unroll
        for (int i = 0; i < 8; i++)
#pragma unroll
            for (int j = 0; j < 8; j++) acc[i][j] = 0.f;

        for (int dc = 0; dc < 4; dc++) {
            __syncthreads();
            for (int t = tid; t < 4096; t += 256) {
                int kk = t >> 2, dq = t & 3;
                float4 v = *(const float4*)&Kg[((size_t)bh * 1024 + kk) * 64 + dc * 16 + dq * 4];
                KT[(dq*4+0)*KT_STRIDE + kk] = v.x;
                KT[(dq*4+1)*KT_STRIDE + kk] = v.y;
                KT[(dq*4+2)*KT_STRIDE + kk] = v.z;
                KT[(dq*4+3)*KT_STRIDE + kk] = v.w;
            }
            __syncthreads();
#pragma unroll
            for (int dd = 0; dd < 16; dd++) {
                float qv[8];
#pragma unroll
                for (int i = 0; i < 8; i++) qv[i] = Qv[(ty*8+i)*64 + dc*16 + dd];
                float kv[8];
                *(float4*)&kv[0] = *(float4*)&KT[dd*KT_STRIDE + tx*8];
                *(float4*)&kv[4] = *(float4*)&KT[dd*KT_STRIDE + tx*8 + 4];
#pragma unroll
                for (int i = 0; i < 8; i++)
#pragma unroll
                    for (int j = 0; j < 8; j++)
                        acc[i][j] += qv[i] * kv[j];
            }
        }
        float* Sv = var ? S2 : S1;
#pragma unroll
        for (int j = 0; j < 8; j++) {
            int k = tx * 8 + j;
            bool masked = (pad[b * 1024 + k] == 0);
#pragma unroll
            for (int i = 0; i < 8; i++) {
                float v = acc[i][j] * 0.125f;
                Sv[(ty*8+i)*1024 + k] = masked ? -1e9f : v;
            }
        }
        __syncthreads();
    }

    {
        const int warp = tid >> 5, lane = tid & 31;
        for (int task = warp; task < 32; task += 8) {
            int var = task >> 4;
            int q   = task & 15;
            float* row = (var ? S2 : S1) + q * 1024;
            float vreg[32];
            float m = -3.4e38f;
#pragma unroll
            for (int j = 0; j < 32; j++) { vreg[j] = row[lane + 32*j]; m = fmaxf(m, vreg[j]); }
#pragma unroll
            for (int o = 16; o > 0; o >>= 1) m = fmaxf(m, __shfl_xor_sync(0xffffffffu, m, o));
            float s = 0.f;
#pragma unroll
            for (int j = 0; j < 32; j++) { vreg[j] = __expf(vreg[j] - m); s += vreg[j]; }
#pragma unroll
            for (int o = 16; o > 0; o >>= 1) s += __shfl_xor_sync(0xffffffffu, s, o);
            float r = 1.0f / s;
            float* gout = (var ? attn2 : attn1) + ((size_t)bh * 1024 + qbase + q) * 1024;
#pragma unroll
            for (int j = 0; j < 32; j++) {
                float e = vreg[j] * r;
                row[lane + 32*j]  = e;
                gout[lane + 32*j] = e;
            }
        }
    }
    __syncthreads();

    for (int t = tid; t < 16384; t += 256) {
        int q = t >> 10, k = t & 1023;
        float c = Cmask[((size_t)b * 1024 + qbase + q) * 1024 + k];
        S1[t] = c * (S1[t] - lam * S2[t]);
    }
    __syncthreads();

    {
        const int pos = tid & 31;
        const int ks  = tid >> 5;
        const int qg  = pos >> 3;
        const int dgp = pos & 7;
        float acc2[4][8];
#pragma unroll
        for (int i = 0; i < 4; i++)
#pragma unroll
            for (int j = 0; j < 8; j++) acc2[i][j] = 0.f;

        float* VT = KT;
        for (int ch = 0; ch < 8; ch++) {
            __syncthreads();
            for (int t = tid; t < 2048; t += 256) {
                int kk = t >> 4, dq = t & 15;
                float4 v = *(const float4*)&gV[((size_t)bh * 1024 + ch * 128 + kk) * 64 + dq * 4];
                *(float4*)&VT[kk * 68 + dq * 4] = v;
            }
            __syncthreads();
            int klo = ks * 16;
#pragma unroll 4
            for (int k = klo; k < klo + 16; k++) {
                float cb[4];
#pragma unroll
                for (int i = 0; i < 4; i++) cb[i] = S1[(qg*4+i)*1024 + ch*128 + k];
                float vv[8];
                *(float4*)&vv[0] = *(float4*)&VT[k*68 + dgp*8];
                *(float4*)&vv[4] = *(float4*)&VT[k*68 + dgp*8 + 4];
#pragma unroll
                for (int i = 0; i < 4; i++)
#pragma unroll
                    for (int j = 0; j < 8; j++)
                        acc2[i][j] += cb[i] * vv[j];
            }
        }
        __syncthreads();
#pragma unroll
        for (int i = 0; i < 4; i++)
#pragma unroll
            for (int j = 0; j < 8; j++)
                S2[(ks*16 + qg*4 + i) * 64 + dgp*8 + j] = acc2[i][j];
        __syncthreads();
        for (int t = tid; t < 1024; t += 256) {
            int q = t >> 6, d = t & 63;
            float ssum = 0.f;
#pragma unroll
            for (int k2 = 0; k2 < 8; k2++) ssum += S2[(k2*16 + q) * 64 + d];
            gCtx[((size_t)b * 1024 + qbase + q) * 1024 + h * 64 + d] = ssum;
        }
    }
}

// ---------------------------------------------------------------------------
// Kernel C1: GroupNorm stats -> folded per-(b,d) scale/bias
// ---------------------------------------------------------------------------
__global__ void stats_kernel(const float* __restrict__ gnw,
                             const float* __restrict__ gnb)
{
    const int bh = blockIdx.x;
    const int b = bh >> 4, h = bh & 15;
    const int tid = threadIdx.x;
    __shared__ float rs[256], rq[256];
    float s = 0.f, sq = 0.f;
    for (int t = tid; t < 65536; t += 256) {
        int srow = t >> 6, d = t & 63;
        float x = gCtx[((size_t)b * 1024 + srow) * 1024 + h * 64 + d];
        s += x; sq += x * x;
    }
    rs[tid] = s; rq[tid] = sq;
    __syncthreads();
    for (int o = 128; o > 0; o >>= 1) {
        if (tid < o) { rs[tid] += rs[tid + o]; rq[tid] += rq[tid + o]; }
        __syncthreads();
    }
    if (tid < 64) {
        float mean = rs[0] * (1.0f / 65536.0f);
        float var  = rq[0] * (1.0f / 65536.0f) - mean * mean;
        float rstd = rsqrtf(var + 1e-5f);
        int d = h * 64 + tid;
        float w = gnw[d];
        float scl = rstd * w * 0.19999999999999996f;
        gScaleArr[b * 1024 + d] = scl;
        gBiasArr [b * 1024 + d] = (gnb[d] - mean * rstd * w) * 0.19999999999999996f;
    }
}

// ---------------------------------------------------------------------------
// Launch
// ---------------------------------------------------------------------------
extern "C" void kernel_launch(void* const* d_in, const int* in_sizes, int n_in,
                              void* d_out, int out_size)
{
    const float* x    = (const float*)d_in[0];
    const float* lam  = (const float*)d_in[1];
    const float* C    = (const float*)d_in[2];
    const int*   pad  = (const int*)  d_in[3];
    const float* wq   = (const float*)d_in[4];
    const float* wqb  = (const float*)d_in[5];
    const float* wk   = (const float*)d_in[6];
    const float* wkb  = (const float*)d_in[7];
    const float* wv   = (const float*)d_in[8];
    const float* wvb  = (const float*)d_in[9];
    const float* wo   = (const float*)d_in[10];
    const float* wob  = (const float*)d_in[11];
    const float* gnw  = (const float*)d_in[12];
    const float* gnb  = (const float*)d_in[13];

    float* out   = (float*)d_out;
    float* attn1 = out + (size_t)BB * SS * DD;
    float* attn2 = attn1 + (size_t)BB * HH * SS * SS;

    cudaFuncSetAttribute(attn_kernel, cudaFuncAttributeMaxDynamicSharedMemorySize,
                         SMEM_FLOATS * (int)sizeof(float));

    mma_gemm<0><<<dim3(40, 32), 256>>>(x, wq, wqb, wk, wkb, wv, wvb,
                                       nullptr, nullptr, nullptr);
    attn_kernel<<<dim3(64, 16, 4), 256, SMEM_FLOATS * sizeof(float)>>>(C, pad, lam, attn1, attn2);
    stats_kernel<<<64, 256>>>(gnw, gnb);
    mma_gemm<1><<<dim3(8, 32), 256>>>(nullptr, nullptr, nullptr, nullptr, nullptr,
                                      nullptr, nullptr, wo, wob, out);
}

// round 4
// speedup vs baseline: 1.4814x; 1.0980x over previous
#include <cuda_runtime.h>
#include <cuda_bf16.h>
#include <cstdint>

// Problem constants
#define BB 4
#define SS 1024
#define DD 1024
#define HH 16
#define DH 64

// Scratch (device globals; no allocation at runtime)
__device__ float gQ1[BB*HH*SS*DH];
__device__ float gQ2[BB*HH*SS*DH];
__device__ float gK1[BB*HH*SS*DH];
__device__ float gK2[BB*HH*SS*DH];
__device__ float gV [BB*HH*SS*DH];
__device__ float gCtx[BB*SS*DD];
__device__ float gScaleArr[BB*DD];
__device__ float gBiasArr [BB*DD];

// ===========================================================================
// mma.sync helpers (base PTX, assembles for sm_103)
// ===========================================================================
static __device__ __forceinline__ uint32_t smem_u32(const void* p) {
    uint32_t a;
    asm("{ .reg .u64 t; cvta.to.shared.u64 t, %1; cvt.u32.u64 %0, t; }"
        : "=r"(a) : "l"(p));
    return a;
}

static __device__ __forceinline__ void ldm_x4(uint32_t* r, uint32_t addr) {
    asm volatile("ldmatrix.sync.aligned.m8n8.x4.shared.b16 {%0,%1,%2,%3}, [%4];"
                 : "=r"(r[0]), "=r"(r[1]), "=r"(r[2]), "=r"(r[3]) : "r"(addr));
}
static __device__ __forceinline__ void ldm_x4_t(uint32_t* r, uint32_t addr) {
    asm volatile("ldmatrix.sync.aligned.m8n8.x4.trans.shared.b16 {%0,%1,%2,%3}, [%4];"
                 : "=r"(r[0]), "=r"(r[1]), "=r"(r[2]), "=r"(r[3]) : "r"(addr));
}

static __device__ __forceinline__ void mma16816(float* c, const uint32_t* a,
                                                const uint32_t* b) {
    asm volatile(
        "mma.sync.aligned.m16n8k16.row.col.f32.bf16.bf16.f32 "
        "{%0,%1,%2,%3}, {%4,%5,%6,%7}, {%8,%9}, {%0,%1,%2,%3};"
        : "+f"(c[0]), "+f"(c[1]), "+f"(c[2]), "+f"(c[3])
        : "r"(a[0]), "r"(a[1]), "r"(a[2]), "r"(a[3]), "r"(b[0]), "r"(b[1]));
}

// split 2 fp32 -> packed bf16x2 hi and lo
static __device__ __forceinline__ void splitpair(float f0, float f1,
                                                 uint32_t& h, uint32_t& l) {
    __nv_bfloat16 h0 = __float2bfloat16(f0);
    __nv_bfloat16 h1 = __float2bfloat16(f1);
    __nv_bfloat16 l0 = __float2bfloat16(f0 - __bfloat162float(h0));
    __nv_bfloat16 l1 = __float2bfloat16(f1 - __bfloat162float(h1));
    __nv_bfloat162 hp; hp.x = h0; hp.y = h1;
    __nv_bfloat162 lp; lp.x = l0; lp.y = l1;
    h = *reinterpret_cast<uint32_t*>(&hp);
    l = *reinterpret_cast<uint32_t*>(&lp);
}

// split fp32 float4 -> hi/lo bf16 uint2 pair
static __device__ __forceinline__ void split4(float4 v, uint2& hv, uint2& lv) {
    uint32_t h0, l0, h1, l1;
    splitpair(v.x, v.y, h0, l0);
    splitpair(v.z, v.w, h1, l1);
    hv = make_uint2(h0, h1);
    lv = make_uint2(l0, l1);
}

// fast exp on the FMA pipe (x <= 0 after max-subtraction); ~2e-7 rel err
static __device__ __forceinline__ float fexp(float x) {
    float t = x * 1.4426950408889634f;
    t = fmaxf(t, -126.0f);
    float fl = floorf(t);
    float f = t - fl;
    float p = 1.33335581e-3f;
    p = fmaf(p, f, 9.61812910e-3f);
    p = fmaf(p, f, 5.55041087e-2f);
    p = fmaf(p, f, 2.40226507e-1f);
    p = fmaf(p, f, 6.93147180e-1f);
    p = fmaf(p, f, 1.0f);
    return p * __int_as_float(((int)fl + 127) << 23);
}

// smem tile byte offset with ldmatrix-friendly swizzle (mma_gemm tiles)
// tile: rows x 32 bf16 (64B/row = 4 x 16B chunks), chunk ^= (row>>1)&3
static __device__ __forceinline__ uint32_t sw_off(int row, int chunk) {
    return (uint32_t)(row * 64 + ((chunk ^ ((row >> 1) & 3)) << 4));
}

// ===========================================================================
// mma_gemm<MODE>: C[m0:+128, n0:+128] = A @ W^T + bias, K=1024, split-bf16.
// MODE 0: A = X; W/bias = qkv sections; scatter to per-head fp32 buffers.
// MODE 1: A = gCtx folded with gScaleArr/gBiasArr; W = Wo; writes out.
// ===========================================================================
template<int MODE>
__global__ __launch_bounds__(256, 2)
void mma_gemm(const float* __restrict__ Ain,
              const float* __restrict__ wq, const float* __restrict__ wqb,
              const float* __restrict__ wk, const float* __restrict__ wkb,
              const float* __restrict__ wv, const float* __restrict__ wvb,
              const float* __restrict__ Wo, const float* __restrict__ ob,
              float* __restrict__ out)
{
    __shared__ __align__(16) char sm[32768];
    char* Ahi = sm;
    char* Alo = sm + 8192;
    char* Bhi = sm + 16384;
    char* Blo = sm + 24576;

    const int tid  = threadIdx.x;
    const int lane = tid & 31;
    const int warp = tid >> 5;
    const int wm   = warp >> 1;
    const int wn   = warp & 1;
    const int n0 = blockIdx.x * 128;
    const int m0 = blockIdx.y * 128;
    const int b  = m0 >> 10;

    const float* A = (MODE == 0) ? Ain : gCtx;
    const float* W;
    const float* Wb;
    if (MODE == 0) {
        if (n0 < 2048)      { W = wq + (size_t)n0 * 1024;          Wb = wqb + n0; }
        else if (n0 < 4096) { W = wk + (size_t)(n0 - 2048) * 1024; Wb = wkb + (n0 - 2048); }
        else                { W = wv + (size_t)(n0 - 4096) * 1024; Wb = wvb + (n0 - 4096); }
    } else {
        W = Wo + (size_t)n0 * 1024; Wb = ob + n0;
    }

    const uint32_t AhiU = smem_u32(Ahi), AloU = smem_u32(Alo);
    const uint32_t BhiU = smem_u32(Bhi), BloU = smem_u32(Blo);

    float acc[2][8][4];
#pragma unroll
    for (int i = 0; i < 2; i++)
#pragma unroll
        for (int j = 0; j < 8; j++)
#pragma unroll
            for (int v = 0; v < 4; v++) acc[i][j][v] = 0.f;

    const int ldrow = tid >> 1;
    const int ldf4b = (tid & 1) * 4;

    for (int c = 0; c < 32; c++) {
        const int k0 = c * 32;
        {
            const float* src = A + (size_t)(m0 + ldrow) * 1024 + k0 + ldf4b * 4;
#pragma unroll
            for (int i = 0; i < 4; i++) {
                float4 v = *(const float4*)(src + i * 4);
                if (MODE == 1) {
                    int kc = k0 + ldf4b * 4 + i * 4;
                    float4 sc = *(const float4*)&gScaleArr[b * 1024 + kc];
                    float4 bi = *(const float4*)&gBiasArr [b * 1024 + kc];
                    v.x = v.x * sc.x + bi.x; v.y = v.y * sc.y + bi.y;
                    v.z = v.z * sc.z + bi.z; v.w = v.w * sc.w + bi.w;
                }
                uint2 hv, lv;
                split4(v, hv, lv);
                int f4 = ldf4b + i;
                uint32_t off = sw_off(ldrow, f4 >> 1) + (f4 & 1) * 8;
                *(uint2*)(Ahi + off) = hv;
                *(uint2*)(Alo + off) = lv;
            }
        }
        {
            const float* src = W + (size_t)ldrow * 1024 + k0 + ldf4b * 4;
#pragma unroll
            for (int i = 0; i < 4; i++) {
                float4 v = *(const float4*)(src + i * 4);
                uint2 hv, lv;
                split4(v, hv, lv);
                int f4 = ldf4b + i;
                uint32_t off = sw_off(ldrow, f4 >> 1) + (f4 & 1) * 8;
                *(uint2*)(Bhi + off) = hv;
                *(uint2*)(Blo + off) = lv;
            }
        }
        __syncthreads();

#pragma unroll
        for (int kk = 0; kk < 2; kk++) {
            uint32_t ah[2][4], al[2][4];
            const int arow = wm * 32 + (lane & 7) + (((lane >> 3) & 1) << 3);
            const int achunk = kk * 2 + (lane >> 4);
#pragma unroll
            for (int mi = 0; mi < 2; mi++) {
                uint32_t off = sw_off(arow + mi * 16, achunk);
                ldm_x4(ah[mi], AhiU + off);
                ldm_x4(al[mi], AloU + off);
            }
            const int brow0 = wn * 64 + (lane & 7) + ((lane >> 4) << 3);
            const int bchunk = kk * 2 + ((lane >> 3) & 1);
#pragma unroll
            for (int half = 0; half < 2; half++) {
                uint32_t bh[2][4], bl[2][4];
#pragma unroll
                for (int j = 0; j < 2; j++) {
                    uint32_t off = sw_off(brow0 + half * 32 + j * 16, bchunk);
                    ldm_x4(bh[j], BhiU + off);
                    ldm_x4(bl[j], BloU + off);
                }
#pragma unroll
                for (int mi = 0; mi < 2; mi++)
#pragma unroll
                    for (int j = 0; j < 2; j++)
#pragma unroll
                        for (int s = 0; s < 2; s++) {
                            float* cp = acc[mi][half * 4 + j * 2 + s];
                            mma16816(cp, ah[mi], &bh[j][s * 2]);
                            mma16816(cp, ah[mi], &bl[j][s * 2]);
                            mma16816(cp, al[mi], &bh[j][s * 2]);
                        }
            }
        }
        __syncthreads();
    }

    if (MODE == 0) {
        const int sect = n0 >> 10;
        float* dst = (sect == 0) ? gQ1 : (sect == 1) ? gQ2 :
                     (sect == 2) ? gK1 : (sect == 3) ? gK2 : gV;
#pragma unroll
        for (int mi = 0; mi < 2; mi++) {
            int m = m0 + wm * 32 + mi * 16 + (lane >> 2);
            int s = m & 1023;
#pragma unroll
            for (int nh = 0; nh < 8; nh++) {
                int nl = wn * 64 + nh * 8 + 2 * (lane & 3);
                int nn = (n0 & 1023) + nl;
                int h = nn >> 6, dh = nn & 63;
                float b0 = Wb[nl], b1 = Wb[nl + 1];
                size_t base = ((size_t)((b << 4) + h) * 1024 + s) * 64 + dh;
                float2 v0; v0.x = acc[mi][nh][0] + b0; v0.y = acc[mi][nh][1] + b1;
                float2 v1; v1.x = acc[mi][nh][2] + b0; v1.y = acc[mi][nh][3] + b1;
                *(float2*)&dst[base]          = v0;
                *(float2*)&dst[base + 8 * 64] = v1;
            }
        }
    } else {
#pragma unroll
        for (int mi = 0; mi < 2; mi++) {
            int m = m0 + wm * 32 + mi * 16 + (lane >> 2);
#pragma unroll
            for (int nh = 0; nh < 8; nh++) {
                int nl = wn * 64 + nh * 8 + 2 * (lane & 3);
                float b0 = Wb[nl], b1 = Wb[nl + 1];
                float2 v0; v0.x = acc[mi][nh][0] + b0; v0.y = acc[mi][nh][1] + b1;
                float2 v1; v1.x = acc[mi][nh][2] + b0; v1.y = acc[mi][nh][3] + b1;
                *(float2*)&out[(size_t)m * 1024 + n0 + nl]       = v0;
                *(float2*)&out[(size_t)(m + 8) * 1024 + n0 + nl] = v1;
            }
        }
    }
}

// ===========================================================================
// attn_kernel: per (b, h, 16-query tile), tensor-core scores + ctx,
// FMA-pipe softmax exp.
// smem (bytes): S1 fp32[16][1032] | S2 fp32[16][1032] | KVhi 16KB | KVlo 16KB
//               | QS fp32[2][16][72]
// ===========================================================================
#define SD 1032
#define ATTN_SMEM (66048 + 66048 + 16384 + 16384 + 9216)

__global__ __launch_bounds__(256, 1)
void attn_kernel(const float* __restrict__ Cmask,
                 const int*   __restrict__ pad,
                 const float* __restrict__ lamp,
                 float* __restrict__ attn1,
                 float* __restrict__ attn2)
{
    extern __shared__ char smc[];
    float* S1 = (float*)smc;
    float* S2 = (float*)(smc + 66048);
    char* KVhi = smc + 132096;
    char* KVlo = smc + 148480;
    float* QS  = (float*)(smc + 164864);

    const int qt = blockIdx.x;
    const int h  = blockIdx.y;
    const int b  = blockIdx.z;
    const int tid  = threadIdx.x;
    const int wid  = tid >> 5;
    const int lane = tid & 31;
    const int bh = b * 16 + h;
    const int qbase = qt * 16;

    const uint32_t KVhiU = smem_u32(KVhi), KVloU = smem_u32(KVlo);
    const int r  = lane >> 2;
    const int c2 = (lane & 3) * 2;

    // stage Q tiles (both variants), fp32, padded stride 72
    for (int t = tid; t < 1024; t += 256) {
        int q = t >> 6, d = t & 63;
        QS[q * 72 + d]        = gQ1[((size_t)bh * 1024 + qbase + q) * 64 + d];
        QS[1152 + q * 72 + d] = gQ2[((size_t)bh * 1024 + qbase + q) * 64 + d];
    }
    __syncthreads();

    // ---- Phase 1: scores via mma ----
    for (int var = 0; var < 2; var++) {
        const float* Kg = var ? gK2 : gK1;
        float* Sv = var ? S2 : S1;
        const float* Qv = QS + var * 1152;

        // Q fragments for 4 k16 steps (held in regs for the whole key loop)
        uint32_t qh[4][4], ql[4][4];
#pragma unroll
        for (int kk = 0; kk < 4; kk++) {
            int cb = kk * 16 + c2;
            splitpair(Qv[r*72+cb],        Qv[r*72+cb+1],        qh[kk][0], ql[kk][0]);
            splitpair(Qv[(r+8)*72+cb],    Qv[(r+8)*72+cb+1],    qh[kk][1], ql[kk][1]);
            splitpair(Qv[r*72+cb+8],      Qv[r*72+cb+9],        qh[kk][2], ql[kk][2]);
            splitpair(Qv[(r+8)*72+cb+8],  Qv[(r+8)*72+cb+9],    qh[kk][3], ql[kk][3]);
        }

        for (int ch = 0; ch < 8; ch++) {
            __syncthreads();
            // stage K chunk 128x64 fp32 -> hi/lo bf16 swizzled
            for (int t = tid; t < 2048; t += 256) {
                int row = t >> 4, f4 = t & 15;
                float4 v = *(const float4*)&Kg[((size_t)bh * 1024 + ch * 128 + row) * 64 + f4 * 4];
                uint2 hv, lv;
                split4(v, hv, lv);
                uint32_t off = row * 128 + (((f4 >> 1) ^ (row & 7)) << 4) + (f4 & 1) * 8;
                *(uint2*)(KVhi + off) = hv;
                *(uint2*)(KVlo + off) = lv;
            }
            __syncthreads();

            float c0[4] = {0, 0, 0, 0}, c1[4] = {0, 0, 0, 0};
            const int brow = wid * 16 + (lane & 7) + ((lane >> 4) << 3);
#pragma unroll
            for (int kk = 0; kk < 4; kk++) {
                int bch = kk * 2 + ((lane >> 3) & 1);
                uint32_t off = brow * 128 + ((bch ^ (brow & 7)) << 4);
                uint32_t bhf[4], blf[4];
                ldm_x4(bhf, KVhiU + off);
                ldm_x4(blf, KVloU + off);
                mma16816(c0, qh[kk], &bhf[0]);
                mma16816(c0, qh[kk], &blf[0]);
                mma16816(c0, ql[kk], &bhf[0]);
                mma16816(c1, qh[kk], &bhf[2]);
                mma16816(c1, qh[kk], &blf[2]);
                mma16816(c1, ql[kk], &bhf[2]);
            }
            const int col = ch * 128 + wid * 16 + c2;
            float2 v;
            v.x = c0[0] * 0.125f; v.y = c0[1] * 0.125f; *(float2*)&Sv[r*SD + col] = v;
            v.x = c0[2] * 0.125f; v.y = c0[3] * 0.125f; *(float2*)&Sv[(r+8)*SD + col] = v;
            v.x = c1[0] * 0.125f; v.y = c1[1] * 0.125f; *(float2*)&Sv[r*SD + col + 8] = v;
            v.x = c1[2] * 0.125f; v.y = c1[3] * 0.125f; *(float2*)&Sv[(r+8)*SD + col + 8] = v;
        }
    }
    __syncthreads();

    // ---- Softmax (32 row-tasks over 8 warps), poly exp on FMA pipe ----
    {
        const float lamv = lamp[0]; (void)lamv;
        for (int task = wid; task < 32; task += 8) {
            int var = task >> 4;
            int q   = task & 15;
            float* row = (var ? S2 : S1) + q * SD;
            float vreg[32];
            float m = -3.4e38f;
#pragma unroll
            for (int j = 0; j < 32; j++) {
                int k = lane + 32 * j;
                float v = row[k];
                if (pad[b * 1024 + k] == 0) v = -1e9f;
                vreg[j] = v;
                m = fmaxf(m, v);
            }
#pragma unroll
            for (int o = 16; o > 0; o >>= 1) m = fmaxf(m, __shfl_xor_sync(0xffffffffu, m, o));
            float s = 0.f;
#pragma unroll
            for (int j = 0; j < 32; j++) { vreg[j] = fexp(vreg[j] - m); s += vreg[j]; }
#pragma unroll
            for (int o = 16; o > 0; o >>= 1) s += __shfl_xor_sync(0xffffffffu, s, o);
            float rr = 1.0f / s;
            float* gout = (var ? attn2 : attn1) + ((size_t)bh * 1024 + qbase + q) * 1024;
#pragma unroll
            for (int j = 0; j < 32; j++) {
                float e = vreg[j] * rr;
                row[lane + 32 * j]  = e;
                gout[lane + 32 * j] = e;
            }
        }
    }
    __syncthreads();

    // ---- Combine: S1 <- C * (attn1 - lam * attn2) ----
    {
        const float lam = lamp[0];
        for (int t = tid; t < 16384; t += 256) {
            int q = t >> 10, k = t & 1023;
            float c = Cmask[((size_t)b * 1024 + qbase + q) * 1024 + k];
            S1[q * SD + k] = c * (S1[q * SD + k] - lam * S2[q * SD + k]);
        }
    }

    // ---- Phase 2: ctx = combined @ V via mma; warp wid owns dh cols wid*8..+8 ----
    {
        float cacc[4] = {0, 0, 0, 0};
        for (int ch = 0; ch < 8; ch++) {
            __syncthreads();
            // stage V chunk 128x64 fp32 -> hi/lo bf16 swizzled
            for (int t = tid; t < 2048; t += 256) {
                int row = t >> 4, f4 = t & 15;
                float4 v = *(const float4*)&gV[((size_t)bh * 1024 + ch * 128 + row) * 64 + f4 * 4];
                uint2 hv, lv;
                split4(v, hv, lv);
                uint32_t off = row * 128 + (((f4 >> 1) ^ (row & 7)) << 4) + (f4 & 1) * 8;
                *(uint2*)(KVhi + off) = hv;
                *(uint2*)(KVlo + off) = lv;
            }
            __syncthreads();

#pragma unroll
            for (int k2 = 0; k2 < 4; k2++) {
                int lrow = k2 * 32 + (lane >> 3) * 8 + (lane & 7);
                uint32_t off = lrow * 128 + ((wid ^ (lrow & 7)) << 4);
                uint32_t bhf[4], blf[4];
                ldm_x4_t(bhf, KVhiU + off);
                ldm_x4_t(blf, KVloU + off);
#pragma unroll
                for (int sub = 0; sub < 2; sub++) {
                    int kb = ch * 128 + k2 * 32 + sub * 16;
                    uint32_t ah[4], al[4];
                    splitpair(S1[r*SD+kb+c2],       S1[r*SD+kb+c2+1],       ah[0], al[0]);
                    splitpair(S1[(r+8)*SD+kb+c2],   S1[(r+8)*SD+kb+c2+1],   ah[1], al[1]);
                    splitpair(S1[r*SD+kb+8+c2],     S1[r*SD+kb+8+c2+1],     ah[2], al[2]);
                    splitpair(S1[(r+8)*SD+kb+8+c2], S1[(r+8)*SD+kb+8+c2+1], ah[3], al[3]);
                    mma16816(cacc, ah, &bhf[sub * 2]);
                    mma16816(cacc, ah, &blf[sub * 2]);
                    mma16816(cacc, al, &bhf[sub * 2]);
                }
            }
        }
        // write ctx: rows r, r+8; cols h*64 + wid*8 + c2
        size_t base = ((size_t)(b * 1024 + qbase + r)) * 1024 + h * 64 + wid * 8 + c2;
        float2 v0; v0.x = cacc[0]; v0.y = cacc[1];
        float2 v1; v1.x = cacc[2]; v1.y = cacc[3];
        *(float2*)&gCtx[base]             = v0;
        *(float2*)&gCtx[base + 8 * 1024]  = v1;
    }
}

// ---------------------------------------------------------------------------
// Kernel C1: GroupNorm stats -> folded per-(b,d) scale/bias
// ---------------------------------------------------------------------------
__global__ void stats_kernel(const float* __restrict__ gnw,
                             const float* __restrict__ gnb)
{
    const int bh = blockIdx.x;
    const int b = bh >> 4, h = bh & 15;
    const int tid = threadIdx.x;
    __shared__ float rs[256], rq[256];
    float s = 0.f, sq = 0.f;
    for (int t = tid; t < 65536; t += 256) {
        int srow = t >> 6, d = t & 63;
        float x = gCtx[((size_t)b * 1024 + srow) * 1024 + h * 64 + d];
        s += x; sq += x * x;
    }
    rs[tid] = s; rq[tid] = sq;
    __syncthreads();
    for (int o = 128; o > 0; o >>= 1) {
        if (tid < o) { rs[tid] += rs[tid + o]; rq[tid] += rq[tid + o]; }
        __syncthreads();
    }
    if (tid < 64) {
        float mean = rs[0] * (1.0f / 65536.0f);
        float var  = rq[0] * (1.0f / 65536.0f) - mean * mean;
        float rstd = rsqrtf(var + 1e-5f);
        int d = h * 64 + tid;
        float w = gnw[d];
        float scl = rstd * w * 0.19999999999999996f;
        gScaleArr[b * 1024 + d] = scl;
        gBiasArr [b * 1024 + d] = (gnb[d] - mean * rstd * w) * 0.19999999999999996f;
    }
}

// ---------------------------------------------------------------------------
// Launch
// ---------------------------------------------------------------------------
extern "C" void kernel_launch(void* const* d_in, const int* in_sizes, int n_in,
                              void* d_out, int out_size)
{
    const float* x    = (const float*)d_in[0];
    const float* lam  = (const float*)d_in[1];
    const float* C    = (const float*)d_in[2];
    const int*   pad  = (const int*)  d_in[3];
    const float* wq   = (const float*)d_in[4];
    const float* wqb  = (const float*)d_in[5];
    const float* wk   = (const float*)d_in[6];
    const float* wkb  = (const float*)d_in[7];
    const float* wv   = (const float*)d_in[8];
    const float* wvb  = (const float*)d_in[9];
    const float* wo   = (const float*)d_in[10];
    const float* wob  = (const float*)d_in[11];
    const float* gnw  = (const float*)d_in[12];
    const float* gnb  = (const float*)d_in[13];

    float* out   = (float*)d_out;
    float* attn1 = out + (size_t)BB * SS * DD;
    float* attn2 = attn1 + (size_t)BB * HH * SS * SS;

    cudaFuncSetAttribute(attn_kernel, cudaFuncAttributeMaxDynamicSharedMemorySize,
                         ATTN_SMEM);

    mma_gemm<0><<<dim3(40, 32), 256>>>(x, wq, wqb, wk, wkb, wv, wvb,
                                       nullptr, nullptr, nullptr);
    attn_kernel<<<dim3(64, 16, 4), 256, ATTN_SMEM>>>(C, pad, lam, attn1, attn2);
    stats_kernel<<<64, 256>>>(gnw, gnb);
    mma_gemm<1><<<dim3(8, 32), 256>>>(nullptr, nullptr, nullptr, nullptr, nullptr,
                                      nullptr, nullptr, wo, wob, out);
}

// round 5
// speedup vs baseline: 2.3155x; 1.5630x over previous
#include <cuda_runtime.h>
#include <cuda_bf16.h>
#include <cstdint>

// Problem constants
#define BB 4
#define SS 1024
#define DD 1024
#define HH 16
#define DH 64

// ===========================================================================
// Packed bf16 hi/lo device globals (uint32 = bf16x2 pair along k/dh)
// ===========================================================================
__device__ __align__(16) uint32_t gXh[2097152],  gXl[2097152];   // x      [4096][512]
__device__ __align__(16) uint32_t gWh[2621440],  gWl[2621440];   // wq|wk|wv [5120][512]
__device__ __align__(16) uint32_t gWoh[524288],  gWol[524288];   // wo     [1024][512]
__device__ __align__(16) uint32_t gAh[2097152],  gAl[2097152];   // normalized ctx
__device__ __align__(16) uint32_t gQ1h[2097152], gQ1l[2097152];
__device__ __align__(16) uint32_t gQ2h[2097152], gQ2l[2097152];
__device__ __align__(16) uint32_t gK1h[2097152], gK1l[2097152];
__device__ __align__(16) uint32_t gK2h[2097152], gK2l[2097152];
__device__ __align__(16) uint32_t gVh [2097152], gVl [2097152];
__device__ float gCtx[4194304];
__device__ float gScaleArr[4096];
__device__ float gBiasArr [4096];

// ===========================================================================
// helpers
// ===========================================================================
static __device__ __forceinline__ uint32_t smem_u32(const void* p) {
    uint32_t a;
    asm("{ .reg .u64 t; cvta.to.shared.u64 t, %1; cvt.u32.u64 %0, t; }"
        : "=r"(a) : "l"(p));
    return a;
}
static __device__ __forceinline__ void ldm_x4(uint32_t* r, uint32_t addr) {
    asm volatile("ldmatrix.sync.aligned.m8n8.x4.shared.b16 {%0,%1,%2,%3}, [%4];"
                 : "=r"(r[0]), "=r"(r[1]), "=r"(r[2]), "=r"(r[3]) : "r"(addr));
}
static __device__ __forceinline__ void ldm_x4_t(uint32_t* r, uint32_t addr) {
    asm volatile("ldmatrix.sync.aligned.m8n8.x4.trans.shared.b16 {%0,%1,%2,%3}, [%4];"
                 : "=r"(r[0]), "=r"(r[1]), "=r"(r[2]), "=r"(r[3]) : "r"(addr));
}
static __device__ __forceinline__ void mma16816(float* c, const uint32_t* a,
                                                const uint32_t* b) {
    asm volatile(
        "mma.sync.aligned.m16n8k16.row.col.f32.bf16.bf16.f32 "
        "{%0,%1,%2,%3}, {%4,%5,%6,%7}, {%8,%9}, {%0,%1,%2,%3};"
        : "+f"(c[0]), "+f"(c[1]), "+f"(c[2]), "+f"(c[3])
        : "r"(a[0]), "r"(a[1]), "r"(a[2]), "r"(a[3]), "r"(b[0]), "r"(b[1]));
}
static __device__ __forceinline__ void splitpair(float f0, float f1,
                                                 uint32_t& h, uint32_t& l) {
    __nv_bfloat16 h0 = __float2bfloat16(f0);
    __nv_bfloat16 h1 = __float2bfloat16(f1);
    __nv_bfloat16 l0 = __float2bfloat16(f0 - __bfloat162float(h0));
    __nv_bfloat16 l1 = __float2bfloat16(f1 - __bfloat162float(h1));
    __nv_bfloat162 hp; hp.x = h0; hp.y = h1;
    __nv_bfloat162 lp; lp.x = l0; lp.y = l1;
    h = *reinterpret_cast<uint32_t*>(&hp);
    l = *reinterpret_cast<uint32_t*>(&lp);
}
// fast exp on the FMA pipe
static __device__ __forceinline__ float fexp(float x) {
    float t = x * 1.4426950408889634f;
    t = fmaxf(t, -126.0f);
    float fl = floorf(t);
    float f = t - fl;
    float p = 1.33335581e-3f;
    p = fmaf(p, f, 9.61812910e-3f);
    p = fmaf(p, f, 5.55041087e-2f);
    p = fmaf(p, f, 2.40226507e-1f);
    p = fmaf(p, f, 6.93147180e-1f);
    p = fmaf(p, f, 1.0f);
    return p * __int_as_float(((int)fl + 127) << 23);
}
static __device__ __forceinline__ uint32_t sw_off(int row, int chunk) {
    return (uint32_t)(row * 64 + ((chunk ^ ((row >> 1) & 3)) << 4));
}
#define CPA16(dst, src) \
    asm volatile("cp.async.cg.shared.global [%0], [%1], 16;" :: "r"(dst), "l"(src))
#define CPCOMMIT asm volatile("cp.async.commit_group;" ::: "memory")
#define CPWAIT1  asm volatile("cp.async.wait_group 1;" ::: "memory")
#define CPWAIT0  asm volatile("cp.async.wait_group 0;" ::: "memory")

// ===========================================================================
// prep_split: fp32 -> packed hi/lo bf16.  which: 0=x,1=wq,2=wk,3=wv,4=wo
// ===========================================================================
__global__ void prep_split(const float* __restrict__ src, int which, int npairs)
{
    uint32_t* dh; uint32_t* dl;
    switch (which) {
        case 0: dh = gXh;           dl = gXl;           break;
        case 1: dh = gWh;           dl = gWl;           break;
        case 2: dh = gWh + 1048576; dl = gWl + 1048576; break;
        case 3: dh = gWh + 2097152; dl = gWl + 2097152; break;
        default: dh = gWoh;         dl = gWol;          break;
    }
    int i = blockIdx.x * blockDim.x + threadIdx.x;
    int stride = gridDim.x * blockDim.x;
    for (; i < npairs; i += stride) {
        float2 v = *(const float2*)(src + 2 * (size_t)i);
        uint32_t h, l;
        splitpair(v.x, v.y, h, l);
        dh[i] = h; dl[i] = l;
    }
}

// prep_ctx: gAh/gAl = split(gCtx * scale + bias)
__global__ void prep_ctx()
{
    int i = blockIdx.x * blockDim.x + threadIdx.x;
    int stride = gridDim.x * blockDim.x;
    for (; i < 2097152; i += stride) {
        int m = i >> 9, kp = i & 511, b = m >> 10;
        float2 v  = *(const float2*)&gCtx[(size_t)m * 1024 + 2 * kp];
        float2 sc = *(const float2*)&gScaleArr[b * 1024 + 2 * kp];
        float2 bi = *(const float2*)&gBiasArr [b * 1024 + 2 * kp];
        uint32_t h, l;
        splitpair(v.x * sc.x + bi.x, v.y * sc.y + bi.y, h, l);
        gAh[i] = h; gAl[i] = l;
    }
}

// ===========================================================================
// mma_gemm<MODE>: pure bf16 double-buffered GEMM, 128x128 tile, BK=32.
// MODE 0: A=gX, B=gW (qkv); epilogue -> packed hi/lo per-head Q/K/V.
// MODE 1: A=gA, B=gWo; epilogue -> fp32 out.
// smem: 2 buffers x (Ahi 8K | Alo 8K | Bhi 8K | Blo 8K) = 64KB dynamic.
// ===========================================================================
template<int MODE>
__global__ __launch_bounds__(256, 2)
void mma_gemm(const float* __restrict__ wqb, const float* __restrict__ wkb,
              const float* __restrict__ wvb, const float* __restrict__ ob,
              float* __restrict__ out)
{
    extern __shared__ char sm[];
    const uint32_t smb = smem_u32(sm);
    const int tid  = threadIdx.x;
    const int lane = tid & 31;
    const int warp = tid >> 5;
    const int wm   = warp >> 1;
    const int wn   = warp & 1;
    const int n0 = blockIdx.x * 128;
    const int m0 = blockIdx.y * 128;
    const int b  = m0 >> 10;

    const uint32_t* Ah = (MODE == 0) ? gXh : gAh;
    const uint32_t* Al = (MODE == 0) ? gXl : gAl;
    const uint32_t* Bh = (MODE == 0) ? gWh : gWoh;
    const uint32_t* Bl = (MODE == 0) ? gWl : gWol;
    const float* Wb;
    if (MODE == 0) {
        if (n0 < 2048)      Wb = wqb + n0;
        else if (n0 < 4096) Wb = wkb + (n0 - 2048);
        else                Wb = wvb + (n0 - 4096);
    } else {
        Wb = ob + n0;
    }

    float acc[2][8][4];
#pragma unroll
    for (int i = 0; i < 2; i++)
#pragma unroll
        for (int j = 0; j < 8; j++)
#pragma unroll
            for (int v = 0; v < 4; v++) acc[i][j][v] = 0.f;

    // stage chunk c into buffer buf
#define STAGE_GEMM(c, buf)                                                        \
    {                                                                             \
        _Pragma("unroll")                                                         \
        for (int i = 0; i < 8; i++) {                                             \
            int t = tid + i * 256;                                                \
            int tile = t >> 9;                                                    \
            int r = (t >> 2) & 127;                                               \
            int u = t & 3;                                                        \
            uint32_t dst = smb + (buf) * 32768u + tile * 8192u + sw_off(r, u);    \
            const uint32_t* sa = (tile == 0) ? Ah : (tile == 1) ? Al              \
                                : (tile == 2) ? Bh : Bl;                          \
            const uint32_t* src = sa + (size_t)((tile < 2 ? m0 : n0) + r) * 512   \
                                   + (c) * 16 + u * 4;                            \
            CPA16(dst, src);                                                      \
        }                                                                         \
        CPCOMMIT;                                                                 \
    }

    STAGE_GEMM(0, 0);
    for (int c = 0; c < 32; c++) {
        if (c < 31) { STAGE_GEMM(c + 1, (c + 1) & 1); CPWAIT1; }
        else        { CPWAIT0; }
        __syncthreads();

        const uint32_t base = smb + (c & 1) * 32768u;
        const uint32_t AhiU = base, AloU = base + 8192u;
        const uint32_t BhiU = base + 16384u, BloU = base + 24576u;
#pragma unroll
        for (int kk = 0; kk < 2; kk++) {
            uint32_t ah[2][4], al[2][4];
            const int arow = wm * 32 + (lane & 7) + (((lane >> 3) & 1) << 3);
            const int achunk = kk * 2 + (lane >> 4);
#pragma unroll
            for (int mi = 0; mi < 2; mi++) {
                uint32_t off = sw_off(arow + mi * 16, achunk);
                ldm_x4(ah[mi], AhiU + off);
                ldm_x4(al[mi], AloU + off);
            }
            const int brow0 = wn * 64 + (lane & 7) + ((lane >> 4) << 3);
            const int bchunk = kk * 2 + ((lane >> 3) & 1);
#pragma unroll
            for (int half = 0; half < 2; half++) {
                uint32_t bhf[2][4], blf[2][4];
#pragma unroll
                for (int j = 0; j < 2; j++) {
                    uint32_t off = sw_off(brow0 + half * 32 + j * 16, bchunk);
                    ldm_x4(bhf[j], BhiU + off);
                    ldm_x4(blf[j], BloU + off);
                }
#pragma unroll
                for (int mi = 0; mi < 2; mi++)
#pragma unroll
                    for (int j = 0; j < 2; j++)
#pragma unroll
                        for (int s = 0; s < 2; s++) {
                            float* cp = acc[mi][half * 4 + j * 2 + s];
                            mma16816(cp, ah[mi], &bhf[j][s * 2]);
                            mma16816(cp, ah[mi], &blf[j][s * 2]);
                            mma16816(cp, al[mi], &bhf[j][s * 2]);
                        }
            }
        }
        __syncthreads();
    }
#undef STAGE_GEMM

    if (MODE == 0) {
        const int sect = n0 >> 10;
        uint32_t* dstH = (sect == 0) ? gQ1h : (sect == 1) ? gQ2h :
                         (sect == 2) ? gK1h : (sect == 3) ? gK2h : gVh;
        uint32_t* dstL = (sect == 0) ? gQ1l : (sect == 1) ? gQ2l :
                         (sect == 2) ? gK1l : (sect == 3) ? gK2l : gVl;
#pragma unroll
        for (int mi = 0; mi < 2; mi++) {
            int m = m0 + wm * 32 + mi * 16 + (lane >> 2);
            int s = m & 1023;
#pragma unroll
            for (int nh = 0; nh < 8; nh++) {
                int nl = wn * 64 + nh * 8 + 2 * (lane & 3);
                int nn = (n0 & 1023) + nl;
                int h = nn >> 6, dh = nn & 63;
                float b0 = Wb[nl], b1 = Wb[nl + 1];
                uint32_t h0, l0, h1, l1;
                splitpair(acc[mi][nh][0] + b0, acc[mi][nh][1] + b1, h0, l0);
                splitpair(acc[mi][nh][2] + b0, acc[mi][nh][3] + b1, h1, l1);
                size_t base = ((size_t)((b << 4) + h) * 1024 + s) * 32 + (dh >> 1);
                dstH[base] = h0; dstL[base] = l0;
                dstH[base + 256] = h1; dstL[base + 256] = l1;   // row s+8
            }
        }
    } else {
#pragma unroll
        for (int mi = 0; mi < 2; mi++) {
            int m = m0 + wm * 32 + mi * 16 + (lane >> 2);
#pragma unroll
            for (int nh = 0; nh < 8; nh++) {
                int nl = wn * 64 + nh * 8 + 2 * (lane & 3);
                float b0 = Wb[nl], b1 = Wb[nl + 1];
                float2 v0; v0.x = acc[mi][nh][0] + b0; v0.y = acc[mi][nh][1] + b1;
                float2 v1; v1.x = acc[mi][nh][2] + b0; v1.y = acc[mi][nh][3] + b1;
                *(float2*)&out[(size_t)m * 1024 + n0 + nl]       = v0;
                *(float2*)&out[(size_t)(m + 8) * 1024 + n0 + nl] = v1;
            }
        }
    }
}

// ===========================================================================
// attn_kernel: per (b, h, 16-query tile).
// smem: S1 fp32[16][1032] (66048) | S2 fp32[16][1032] (66048, reused as P hi/lo)
//       | KV staging 2 x (hi 16K + lo 16K) (65536) | padbias (4096)
// ===========================================================================
#define SD 1032
#define OFF_S2  66048u
#define OFF_KV  132096u
#define OFF_PAD 197632u
#define ATTN_SMEM 201728

static __device__ __forceinline__ void stage_kv(uint32_t smb, const uint32_t* sH,
                                                const uint32_t* sL, int bh,
                                                int ch, int buf, int tid)
{
#pragma unroll
    for (int i = 0; i < 8; i++) {
        int t = tid + i * 256;
        int tile = t >> 10;          // 0 = hi, 1 = lo
        int row = (t >> 3) & 127;
        int cu = t & 7;
        uint32_t dst = smb + OFF_KV + buf * 32768u + tile * 16384u +
                       row * 128u + (uint32_t)((cu ^ (row & 7)) << 4);
        const uint32_t* src = (tile ? sL : sH) +
                              ((size_t)bh * 1024 + ch * 128 + row) * 32 + cu * 4;
        CPA16(dst, src);
    }
    CPCOMMIT;
}

__global__ __launch_bounds__(256, 1)
void attn_kernel(const float* __restrict__ Cmask,
                 const int*   __restrict__ pad,
                 const float* __restrict__ lamp,
                 float* __restrict__ attn1,
                 float* __restrict__ attn2)
{
    extern __shared__ char smc[];
    const uint32_t smb = smem_u32(smc);
    float* S1 = (float*)smc;
    float* S2 = (float*)(smc + OFF_S2);
    float* PADB = (float*)(smc + OFF_PAD);
    uint32_t* Phi32 = (uint32_t*)(smc + OFF_S2);
    uint32_t* Plo32 = (uint32_t*)(smc + OFF_S2 + 32768);
    const uint32_t PhiU = smb + OFF_S2;
    const uint32_t PloU = smb + OFF_S2 + 32768u;

    const int qt = blockIdx.x;
    const int h  = blockIdx.y;
    const int b  = blockIdx.z;
    const int tid  = threadIdx.x;
    const int wid  = tid >> 5;
    const int lane = tid & 31;
    const int bh = b * 16 + h;
    const int qbase = qt * 16;
    const int r  = lane >> 2;
    const int c2 = (lane & 3) * 2;

    // pad bias into smem
    for (int t = tid; t < 1024; t += 256)
        PADB[t] = (pad[b * 1024 + t] == 0) ? -1e9f : 0.f;

    // ---- Phase 1: scores, double-buffered cp.async ----
    stage_kv(smb, gK1h, gK1l, bh, 0, 0, tid);
    uint32_t qh[4][4], ql[4][4];
    for (int it = 0; it < 16; it++) {
        const int var = it >> 3, ch = it & 7;
        if (it < 15) {
            int v2 = (it + 1) >> 3;
            stage_kv(smb, v2 ? gK2h : gK1h, v2 ? gK2l : gK1l, bh,
                     (it + 1) & 7, (it + 1) & 1, tid);
            CPWAIT1;
        } else {
            CPWAIT0;
        }
        __syncthreads();

        if (ch == 0) {
            const uint32_t* Qh = var ? gQ2h : gQ1h;
            const uint32_t* Ql = var ? gQ2l : gQ1l;
            size_t qb0 = ((size_t)bh * 1024 + qbase + r) * 32;
            size_t qb1 = qb0 + 8 * 32;
#pragma unroll
            for (int kk = 0; kk < 4; kk++) {
                int p = kk * 8 + (lane & 3);
                qh[kk][0] = Qh[qb0 + p];     ql[kk][0] = Ql[qb0 + p];
                qh[kk][1] = Qh[qb1 + p];     ql[kk][1] = Ql[qb1 + p];
                qh[kk][2] = Qh[qb0 + p + 4]; ql[kk][2] = Ql[qb0 + p + 4];
                qh[kk][3] = Qh[qb1 + p + 4]; ql[kk][3] = Ql[qb1 + p + 4];
            }
        }

        const uint32_t KVhiU = smb + OFF_KV + (it & 1) * 32768u;
        const uint32_t KVloU = KVhiU + 16384u;
        float c0[4] = {0, 0, 0, 0}, c1[4] = {0, 0, 0, 0};
        const int brow = wid * 16 + (lane & 7) + ((lane >> 4) << 3);
#pragma unroll
        for (int kk = 0; kk < 4; kk++) {
            int bch = kk * 2 + ((lane >> 3) & 1);
            uint32_t off = brow * 128 + ((bch ^ (brow & 7)) << 4);
            uint32_t bhf[4], blf[4];
            ldm_x4(bhf, KVhiU + off);
            ldm_x4(blf, KVloU + off);
            mma16816(c0, qh[kk], &bhf[0]);
            mma16816(c0, qh[kk], &blf[0]);
            mma16816(c0, ql[kk], &bhf[0]);
            mma16816(c1, qh[kk], &bhf[2]);
            mma16816(c1, qh[kk], &blf[2]);
            mma16816(c1, ql[kk], &bhf[2]);
        }
        float* Sv = var ? S2 : S1;
        const int col = ch * 128 + wid * 16 + c2;
        float2 v;
        v.x = c0[0] * 0.125f; v.y = c0[1] * 0.125f; *(float2*)&Sv[r*SD + col] = v;
        v.x = c0[2] * 0.125f; v.y = c0[3] * 0.125f; *(float2*)&Sv[(r+8)*SD + col] = v;
        v.x = c1[0] * 0.125f; v.y = c1[1] * 0.125f; *(float2*)&Sv[r*SD + col + 8] = v;
        v.x = c1[2] * 0.125f; v.y = c1[3] * 0.125f; *(float2*)&Sv[(r+8)*SD + col + 8] = v;
        __syncthreads();
    }

    // prefetch V chunk 0 (completes during softmax)
    stage_kv(smb, gVh, gVl, bh, 0, 0, tid);

    // ---- Softmax ----
    for (int task = wid; task < 32; task += 8) {
        int var = task >> 4;
        int q   = task & 15;
        float* row = (var ? S2 : S1) + q * SD;
        float vreg[32];
        float m = -3.4e38f;
#pragma unroll
        for (int j = 0; j < 32; j++) {
            int k = lane + 32 * j;
            float v = row[k] + PADB[k];
            vreg[j] = v;
            m = fmaxf(m, v);
        }
#pragma unroll
        for (int o = 16; o > 0; o >>= 1) m = fmaxf(m, __shfl_xor_sync(0xffffffffu, m, o));
        float s = 0.f;
#pragma unroll
        for (int j = 0; j < 32; j++) { vreg[j] = fexp(vreg[j] - m); s += vreg[j]; }
#pragma unroll
        for (int o = 16; o > 0; o >>= 1) s += __shfl_xor_sync(0xffffffffu, s, o);
        float rr = 1.0f / s;
        float* gout = (var ? attn2 : attn1) + ((size_t)bh * 1024 + qbase + q) * 1024;
#pragma unroll
        for (int j = 0; j < 32; j++) {
            float e = vreg[j] * rr;
            row[lane + 32 * j]  = e;
            gout[lane + 32 * j] = e;
        }
    }
    __syncthreads();

    // ---- Combine pass 1 (in place, fp32): S1 <- C * (a1 - lam*a2) ----
    {
        const float lam = lamp[0];
        for (int t = tid; t < 16384; t += 256) {
            int q = t >> 10, k = t & 1023;
            float c = Cmask[((size_t)b * 1024 + qbase + q) * 1024 + k];
            S1[q * SD + k] = c * (S1[q * SD + k] - lam * S2[q * SD + k]);
        }
    }
    __syncthreads();

    // ---- Combine pass 2: S1 fp32 -> P hi/lo bf16 (chunk-major, XOR units) ----
    for (int pidx = tid; pidx < 8192; pidx += 256) {
        int q = pidx >> 9, kp = pidx & 511;
        int k = kp * 2;
        uint32_t hv, lv;
        splitpair(S1[q * SD + k], S1[q * SD + k + 1], hv, lv);
        int kb16 = k >> 4;
        int colin = k & 15;
        int half = colin >> 3;
        int w = (colin & 7) >> 1;
        int u = q * 2 + (half ^ ((q >> 2) & 1));
        int addr = kb16 * 128 + u * 4 + w;
        Phi32[addr] = hv;
        Plo32[addr] = lv;
    }
    __syncthreads();

    // ---- Phase 2: ctx = P @ V; warp wid owns dh cols wid*8..+8 ----
    {
        const uint32_t ua = (uint32_t)((((lane & 15) * 2 +
                             ((lane >> 4) ^ (((lane & 15) >> 2) & 1)))) << 4);
        float cacc[4] = {0, 0, 0, 0};
        for (int ch = 0; ch < 8; ch++) {
            if (ch < 7) { stage_kv(smb, gVh, gVl, bh, ch + 1, (ch + 1) & 1, tid); CPWAIT1; }
            else        { CPWAIT0; }
            __syncthreads();
            const uint32_t KVhiU = smb + OFF_KV + (ch & 1) * 32768u;
            const uint32_t KVloU = KVhiU + 16384u;
#pragma unroll
            for (int k2 = 0; k2 < 4; k2++) {
                int lrow = k2 * 32 + (lane >> 3) * 8 + (lane & 7);
                uint32_t boff = lrow * 128 + ((wid ^ (lrow & 7)) << 4);
                uint32_t bhf[4], blf[4];
                ldm_x4_t(bhf, KVhiU + boff);
                ldm_x4_t(blf, KVloU + boff);
#pragma unroll
                for (int sub = 0; sub < 2; sub++) {
                    int kb16 = ch * 8 + k2 * 2 + sub;
                    uint32_t ah[4], al[4];
                    ldm_x4(ah, PhiU + kb16 * 512 + ua);
                    ldm_x4(al, PloU + kb16 * 512 + ua);
                    mma16816(cacc, ah, &bhf[sub * 2]);
                    mma16816(cacc, ah, &blf[sub * 2]);
                    mma16816(cacc, al, &bhf[sub * 2]);
                }
            }
            __syncthreads();
        }
        size_t base = ((size_t)(b * 1024 + qbase + r)) * 1024 + h * 64 + wid * 8 + c2;
        float2 v0; v0.x = cacc[0]; v0.y = cacc[1];
        float2 v1; v1.x = cacc[2]; v1.y = cacc[3];
        *(float2*)&gCtx[base]            = v0;
        *(float2*)&gCtx[base + 8 * 1024] = v1;
    }
}

// ---------------------------------------------------------------------------
// stats_kernel: GroupNorm stats -> folded per-(b,d) scale/bias
// ---------------------------------------------------------------------------
__global__ void stats_kernel(const float* __restrict__ gnw,
                             const float* __restrict__ gnb)
{
    const int bh = blockIdx.x;
    const int b = bh >> 4, h = bh & 15;
    const int tid = threadIdx.x;
    __shared__ float rs[256], rq[256];
    float s = 0.f, sq = 0.f;
    for (int t = tid; t < 65536; t += 256) {
        int srow = t >> 6, d = t & 63;
        float x = gCtx[((size_t)b * 1024 + srow) * 1024 + h * 64 + d];
        s += x; sq += x * x;
    }
    rs[tid] = s; rq[tid] = sq;
    __syncthreads();
    for (int o = 128; o > 0; o >>= 1) {
        if (tid < o) { rs[tid] += rs[tid + o]; rq[tid] += rq[tid + o]; }
        __syncthreads();
    }
    if (tid < 64) {
        float mean = rs[0] * (1.0f / 65536.0f);
        float var  = rq[0] * (1.0f / 65536.0f) - mean * mean;
        float rstd = rsqrtf(var + 1e-5f);
        int d = h * 64 + tid;
        float w = gnw[d];
        float scl = rstd * w * 0.19999999999999996f;
        gScaleArr[b * 1024 + d] = scl;
        gBiasArr [b * 1024 + d] = (gnb[d] - mean * rstd * w) * 0.19999999999999996f;
    }
}

// ---------------------------------------------------------------------------
// Launch
// ---------------------------------------------------------------------------
extern "C" void kernel_launch(void* const* d_in, const int* in_sizes, int n_in,
                              void* d_out, int out_size)
{
    const float* x    = (const float*)d_in[0];
    const float* lam  = (const float*)d_in[1];
    const float* C    = (const float*)d_in[2];
    const int*   pad  = (const int*)  d_in[3];
    const float* wq   = (const float*)d_in[4];
    const float* wqb  = (const float*)d_in[5];
    const float* wk   = (const float*)d_in[6];
    const float* wkb  = (const float*)d_in[7];
    const float* wv   = (const float*)d_in[8];
    const float* wvb  = (const float*)d_in[9];
    const float* wo   = (const float*)d_in[10];
    const float* wob  = (const float*)d_in[11];
    const float* gnw  = (const float*)d_in[12];
    const float* gnb  = (const float*)d_in[13];

    float* out   = (float*)d_out;
    float* attn1 = out + (size_t)BB * SS * DD;
    float* attn2 = attn1 + (size_t)BB * HH * SS * SS;

    cudaFuncSetAttribute(attn_kernel, cudaFuncAttributeMaxDynamicSharedMemorySize,
                         ATTN_SMEM);
    cudaFuncSetAttribute(mma_gemm<0>, cudaFuncAttributeMaxDynamicSharedMemorySize, 65536);
    cudaFuncSetAttribute(mma_gemm<1>, cudaFuncAttributeMaxDynamicSharedMemorySize, 65536);

    prep_split<<<512, 256>>>(x,  0, 2097152);
    prep_split<<<512, 256>>>(wq, 1, 1048576);
    prep_split<<<512, 256>>>(wk, 2, 1048576);
    prep_split<<<512, 256>>>(wv, 3, 524288);
    prep_split<<<512, 256>>>(wo, 4, 524288);

    mma_gemm<0><<<dim3(40, 32), 256, 65536>>>(wqb, wkb, wvb, nullptr, nullptr);
    attn_kernel<<<dim3(64, 16, 4), 256, ATTN_SMEM>>>(C, pad, lam, attn1, attn2);
    stats_kernel<<<64, 256>>>(gnw, gnb);
    prep_ctx<<<512, 256>>>();
    mma_gemm<1><<<dim3(8, 32), 256, 65536>>>(nullptr, nullptr, nullptr, wob, out);
}

// round 6
// speedup vs baseline: 2.6578x; 1.1478x over previous
#include <cuda_runtime.h>
#include <cuda_bf16.h>
#include <cstdint>

// Problem constants
#define BB 4
#define SS 1024
#define DD 1024
#define HH 16
#define DH 64

// ===========================================================================
// Packed bf16 hi/lo device globals (uint32 = bf16x2 pair along k/dh)
// ===========================================================================
__device__ __align__(16) uint32_t gXh[2097152],  gXl[2097152];   // x      [4096][512]
__device__ __align__(16) uint32_t gWh[2621440],  gWl[2621440];   // wq|wk|wv [5120][512]
__device__ __align__(16) uint32_t gWoh[524288],  gWol[524288];   // wo     [1024][512]
__device__ __align__(16) uint32_t gAh[2097152],  gAl[2097152];   // normalized ctx
__device__ __align__(16) uint32_t gQ1h[2097152], gQ1l[2097152];
__device__ __align__(16) uint32_t gQ2h[2097152], gQ2l[2097152];
__device__ __align__(16) uint32_t gK1h[2097152], gK1l[2097152];
__device__ __align__(16) uint32_t gK2h[2097152], gK2l[2097152];
__device__ __align__(16) uint32_t gVh [2097152], gVl [2097152];
__device__ float gCtx[4194304];
__device__ float gScaleArr[4096];
__device__ float gBiasArr [4096];

// ===========================================================================
// helpers
// ===========================================================================
static __device__ __forceinline__ uint32_t smem_u32(const void* p) {
    uint32_t a;
    asm("{ .reg .u64 t; cvta.to.shared.u64 t, %1; cvt.u32.u64 %0, t; }"
        : "=r"(a) : "l"(p));
    return a;
}
static __device__ __forceinline__ void ldm_x4(uint32_t* r, uint32_t addr) {
    asm volatile("ldmatrix.sync.aligned.m8n8.x4.shared.b16 {%0,%1,%2,%3}, [%4];"
                 : "=r"(r[0]), "=r"(r[1]), "=r"(r[2]), "=r"(r[3]) : "r"(addr));
}
static __device__ __forceinline__ void ldm_x2(uint32_t* r, uint32_t addr) {
    asm volatile("ldmatrix.sync.aligned.m8n8.x2.shared.b16 {%0,%1}, [%2];"
                 : "=r"(r[0]), "=r"(r[1]) : "r"(addr));
}
static __device__ __forceinline__ void ldm_x4_t(uint32_t* r, uint32_t addr) {
    asm volatile("ldmatrix.sync.aligned.m8n8.x4.trans.shared.b16 {%0,%1,%2,%3}, [%4];"
                 : "=r"(r[0]), "=r"(r[1]), "=r"(r[2]), "=r"(r[3]) : "r"(addr));
}
static __device__ __forceinline__ void mma16816(float* c, const uint32_t* a,
                                                const uint32_t* b) {
    asm volatile(
        "mma.sync.aligned.m16n8k16.row.col.f32.bf16.bf16.f32 "
        "{%0,%1,%2,%3}, {%4,%5,%6,%7}, {%8,%9}, {%0,%1,%2,%3};"
        : "+f"(c[0]), "+f"(c[1]), "+f"(c[2]), "+f"(c[3])
        : "r"(a[0]), "r"(a[1]), "r"(a[2]), "r"(a[3]), "r"(b[0]), "r"(b[1]));
}
static __device__ __forceinline__ void splitpair(float f0, float f1,
                                                 uint32_t& h, uint32_t& l) {
    __nv_bfloat16 h0 = __float2bfloat16(f0);
    __nv_bfloat16 h1 = __float2bfloat16(f1);
    __nv_bfloat16 l0 = __float2bfloat16(f0 - __bfloat162float(h0));
    __nv_bfloat16 l1 = __float2bfloat16(f1 - __bfloat162float(h1));
    __nv_bfloat162 hp; hp.x = h0; hp.y = h1;
    __nv_bfloat162 lp; lp.x = l0; lp.y = l1;
    h = *reinterpret_cast<uint32_t*>(&hp);
    l = *reinterpret_cast<uint32_t*>(&lp);
}
// fast exp on the FMA pipe
static __device__ __forceinline__ float fexp(float x) {
    float t = x * 1.4426950408889634f;
    t = fmaxf(t, -126.0f);
    float fl = floorf(t);
    float f = t - fl;
    float p = 1.33335581e-3f;
    p = fmaf(p, f, 9.61812910e-3f);
    p = fmaf(p, f, 5.55041087e-2f);
    p = fmaf(p, f, 2.40226507e-1f);
    p = fmaf(p, f, 6.93147180e-1f);
    p = fmaf(p, f, 1.0f);
    return p * __int_as_float(((int)fl + 127) << 23);
}
static __device__ __forceinline__ uint32_t sw_off(int row, int chunk) {
    return (uint32_t)(row * 64 + ((chunk ^ ((row >> 1) & 3)) << 4));
}
#define CPA16(dst, src) \
    asm volatile("cp.async.cg.shared.global [%0], [%1], 16;" :: "r"(dst), "l"(src))
#define CPCOMMIT asm volatile("cp.async.commit_group;" ::: "memory")
#define CPWAIT1  asm volatile("cp.async.wait_group 1;" ::: "memory")
#define CPWAIT0  asm volatile("cp.async.wait_group 0;" ::: "memory")

// ===========================================================================
// prep kernels
// ===========================================================================
__global__ void prep_split(const float* __restrict__ src, int which, int npairs)
{
    uint32_t* dh; uint32_t* dl;
    switch (which) {
        case 0: dh = gXh;           dl = gXl;           break;
        case 1: dh = gWh;           dl = gWl;           break;
        case 2: dh = gWh + 1048576; dl = gWl + 1048576; break;
        case 3: dh = gWh + 2097152; dl = gWl + 2097152; break;
        default: dh = gWoh;         dl = gWol;          break;
    }
    int i = blockIdx.x * blockDim.x + threadIdx.x;
    int stride = gridDim.x * blockDim.x;
    for (; i < npairs; i += stride) {
        float2 v = *(const float2*)(src + 2 * (size_t)i);
        uint32_t h, l;
        splitpair(v.x, v.y, h, l);
        dh[i] = h; dl[i] = l;
    }
}

__global__ void prep_ctx()
{
    int i = blockIdx.x * blockDim.x + threadIdx.x;
    int stride = gridDim.x * blockDim.x;
    for (; i < 2097152; i += stride) {
        int m = i >> 9, kp = i & 511, b = m >> 10;
        float2 v  = *(const float2*)&gCtx[(size_t)m * 1024 + 2 * kp];
        float2 sc = *(const float2*)&gScaleArr[b * 1024 + 2 * kp];
        float2 bi = *(const float2*)&gBiasArr [b * 1024 + 2 * kp];
        uint32_t h, l;
        splitpair(v.x * sc.x + bi.x, v.y * sc.y + bi.y, h, l);
        gAh[i] = h; gAl[i] = l;
    }
}

// ===========================================================================
// mma_gemm<MODE>: pure bf16 double-buffered GEMM, 128x128 tile, BK=32.
// (unchanged from round 5)
// ===========================================================================
template<int MODE>
__global__ __launch_bounds__(256, 2)
void mma_gemm(const float* __restrict__ wqb, const float* __restrict__ wkb,
              const float* __restrict__ wvb, const float* __restrict__ ob,
              float* __restrict__ out)
{
    extern __shared__ char sm[];
    const uint32_t smb = smem_u32(sm);
    const int tid  = threadIdx.x;
    const int lane = tid & 31;
    const int warp = tid >> 5;
    const int wm   = warp >> 1;
    const int wn   = warp & 1;
    const int n0 = blockIdx.x * 128;
    const int m0 = blockIdx.y * 128;
    const int b  = m0 >> 10;

    const uint32_t* Ah = (MODE == 0) ? gXh : gAh;
    const uint32_t* Al = (MODE == 0) ? gXl : gAl;
    const uint32_t* Bh = (MODE == 0) ? gWh : gWoh;
    const uint32_t* Bl = (MODE == 0) ? gWl : gWol;
    const float* Wb;
    if (MODE == 0) {
        if (n0 < 2048)      Wb = wqb + n0;
        else if (n0 < 4096) Wb = wkb + (n0 - 2048);
        else                Wb = wvb + (n0 - 4096);
    } else {
        Wb = ob + n0;
    }

    float acc[2][8][4];
#pragma unroll
    for (int i = 0; i < 2; i++)
#pragma unroll
        for (int j = 0; j < 8; j++)
#pragma unroll
            for (int v = 0; v < 4; v++) acc[i][j][v] = 0.f;

#define STAGE_GEMM(c, buf)                                                        \
    {                                                                             \
        _Pragma("unroll")                                                         \
        for (int i = 0; i < 8; i++) {                                             \
            int t = tid + i * 256;                                                \
            int tile = t >> 9;                                                    \
            int r = (t >> 2) & 127;                                               \
            int u = t & 3;                                                        \
            uint32_t dst = smb + (buf) * 32768u + tile * 8192u + sw_off(r, u);    \
            const uint32_t* sa = (tile == 0) ? Ah : (tile == 1) ? Al              \
                                : (tile == 2) ? Bh : Bl;                          \
            const uint32_t* src = sa + (size_t)((tile < 2 ? m0 : n0) + r) * 512   \
                                   + (c) * 16 + u * 4;                            \
            CPA16(dst, src);                                                      \
        }                                                                         \
        CPCOMMIT;                                                                 \
    }

    STAGE_GEMM(0, 0);
    for (int c = 0; c < 32; c++) {
        if (c < 31) { STAGE_GEMM(c + 1, (c + 1) & 1); CPWAIT1; }
        else        { CPWAIT0; }
        __syncthreads();

        const uint32_t base = smb + (c & 1) * 32768u;
        const uint32_t AhiU = base, AloU = base + 8192u;
        const uint32_t BhiU = base + 16384u, BloU = base + 24576u;
#pragma unroll
        for (int kk = 0; kk < 2; kk++) {
            uint32_t ah[2][4], al[2][4];
            const int arow = wm * 32 + (lane & 7) + (((lane >> 3) & 1) << 3);
            const int achunk = kk * 2 + (lane >> 4);
#pragma unroll
            for (int mi = 0; mi < 2; mi++) {
                uint32_t off = sw_off(arow + mi * 16, achunk);
                ldm_x4(ah[mi], AhiU + off);
                ldm_x4(al[mi], AloU + off);
            }
            const int brow0 = wn * 64 + (lane & 7) + ((lane >> 4) << 3);
            const int bchunk = kk * 2 + ((lane >> 3) & 1);
#pragma unroll
            for (int half = 0; half < 2; half++) {
                uint32_t bhf[2][4], blf[2][4];
#pragma unroll
                for (int j = 0; j < 2; j++) {
                    uint32_t off = sw_off(brow0 + half * 32 + j * 16, bchunk);
                    ldm_x4(bhf[j], BhiU + off);
                    ldm_x4(blf[j], BloU + off);
                }
#pragma unroll
                for (int mi = 0; mi < 2; mi++)
#pragma unroll
                    for (int j = 0; j < 2; j++)
#pragma unroll
                        for (int s = 0; s < 2; s++) {
                            float* cp = acc[mi][half * 4 + j * 2 + s];
                            mma16816(cp, ah[mi], &bhf[j][s * 2]);
                            mma16816(cp, ah[mi], &blf[j][s * 2]);
                            mma16816(cp, al[mi], &bhf[j][s * 2]);
                        }
            }
        }
        __syncthreads();
    }
#undef STAGE_GEMM

    if (MODE == 0) {
        const int sect = n0 >> 10;
        uint32_t* dstH = (sect == 0) ? gQ1h : (sect == 1) ? gQ2h :
                         (sect == 2) ? gK1h : (sect == 3) ? gK2h : gVh;
        uint32_t* dstL = (sect == 0) ? gQ1l : (sect == 1) ? gQ2l :
                         (sect == 2) ? gK1l : (sect == 3) ? gK2l : gVl;
#pragma unroll
        for (int mi = 0; mi < 2; mi++) {
            int m = m0 + wm * 32 + mi * 16 + (lane >> 2);
            int s = m & 1023;
#pragma unroll
            for (int nh = 0; nh < 8; nh++) {
                int nl = wn * 64 + nh * 8 + 2 * (lane & 3);
                int nn = (n0 & 1023) + nl;
                int h = nn >> 6, dh = nn & 63;
                float b0 = Wb[nl], b1 = Wb[nl + 1];
                uint32_t h0, l0, h1, l1;
                splitpair(acc[mi][nh][0] + b0, acc[mi][nh][1] + b1, h0, l0);
                splitpair(acc[mi][nh][2] + b0, acc[mi][nh][3] + b1, h1, l1);
                size_t base = ((size_t)((b << 4) + h) * 1024 + s) * 32 + (dh >> 1);
                dstH[base] = h0; dstL[base] = l0;
                dstH[base + 256] = h1; dstL[base + 256] = l1;
            }
        }
    } else {
#pragma unroll
        for (int mi = 0; mi < 2; mi++) {
            int m = m0 + wm * 32 + mi * 16 + (lane >> 2);
#pragma unroll
            for (int nh = 0; nh < 8; nh++) {
                int nl = wn * 64 + nh * 8 + 2 * (lane & 3);
                float b0 = Wb[nl], b1 = Wb[nl + 1];
                float2 v0; v0.x = acc[mi][nh][0] + b0; v0.y = acc[mi][nh][1] + b1;
                float2 v1; v1.x = acc[mi][nh][2] + b0; v1.y = acc[mi][nh][3] + b1;
                *(float2*)&out[(size_t)m * 1024 + n0 + nl]       = v0;
                *(float2*)&out[(size_t)(m + 8) * 1024 + n0 + nl] = v1;
            }
        }
    }
}

// ===========================================================================
// attn_kernel v2: variant-sequential, 107KB smem -> 2 CTAs/SM.
// smem: S fp32[16][1032] (66048) | KV stage 2x16KB (32768) | Pc 2x4KB (8192)
// ===========================================================================
#define SD 1032
#define OFF_KV 66048u
#define OFF_PC 98816u
#define ATTN_SMEM 107008

// stage 64 keys (hi+lo) of a packed [bh][1024][32-u32] tensor into buf
static __device__ __forceinline__ void stage64(uint32_t smb, const uint32_t* sH,
                                               const uint32_t* sL, int bh,
                                               int ch64, int buf, int tid)
{
#pragma unroll
    for (int i = 0; i < 4; i++) {
        int t = tid + i * 256;            // 0..1023
        int tile = t >> 9;                // 0 = hi, 1 = lo
        int row = (t >> 3) & 63;
        int cu = t & 7;
        uint32_t dst = smb + OFF_KV + buf * 16384u + tile * 8192u +
                       row * 128u + (uint32_t)((cu ^ (row & 7)) << 4);
        const uint32_t* src = (tile ? sL : sH) +
                              ((size_t)bh * 1024 + ch64 * 64 + row) * 32 + cu * 4;
        CPA16(dst, src);
    }
    CPCOMMIT;
}

__global__ __launch_bounds__(256, 2)
void attn_kernel(const float* __restrict__ Cmask,
                 const int*   __restrict__ pad,
                 const float* __restrict__ lamp,
                 float* __restrict__ attn1,
                 float* __restrict__ attn2)
{
    extern __shared__ char smc[];
    const uint32_t smb = smem_u32(smc);
    float* S = (float*)smc;

    const int qt = blockIdx.x;
    const int h  = blockIdx.y;
    const int b  = blockIdx.z;
    const int tid  = threadIdx.x;
    const int wid  = tid >> 5;
    const int lane = tid & 31;
    const int bh = b * 16 + h;
    const int qbase = qt * 16;
    const int r  = lane >> 2;
    const int c2 = (lane & 3) * 2;
    const int* padrow = pad + b * 1024;

    // ---------------- score pass (one variant) ----------------
#define SCORE_PASS(KH, KL, QH, QL)                                               \
    {                                                                            \
        uint32_t qh[4][4], ql[4][4];                                             \
        {                                                                        \
            size_t qb0 = ((size_t)bh * 1024 + qbase + r) * 32;                   \
            size_t qb1 = qb0 + 8 * 32;                                           \
            _Pragma("unroll")                                                    \
            for (int kk = 0; kk < 4; kk++) {                                     \
                int p = kk * 8 + (lane & 3);                                     \
                qh[kk][0] = QH[qb0 + p];     ql[kk][0] = QL[qb0 + p];            \
                qh[kk][1] = QH[qb1 + p];     ql[kk][1] = QL[qb1 + p];            \
                qh[kk][2] = QH[qb0 + p + 4]; ql[kk][2] = QL[qb0 + p + 4];        \
                qh[kk][3] = QH[qb1 + p + 4]; ql[kk][3] = QL[qb1 + p + 4];        \
            }                                                                    \
        }                                                                        \
        for (int ch = 0; ch < 16; ch++) {                                        \
            CPWAIT0;                                                             \
            __syncthreads();                                                     \
            if (ch < 15) stage64(smb, KH, KL, bh, ch + 1, (ch + 1) & 1, tid);    \
            const uint32_t KVhiU = smb + OFF_KV + (ch & 1) * 16384u;             \
            const uint32_t KVloU = KVhiU + 8192u;                                \
            float c0[4] = {0.f, 0.f, 0.f, 0.f};                                  \
            const int brow = wid * 8 + (lane & 7);                               \
            _Pragma("unroll")                                                    \
            for (int kk = 0; kk < 4; kk++) {                                     \
                int bch = kk * 2 + ((lane >> 3) & 1);                            \
                uint32_t off = brow * 128 + ((bch ^ (brow & 7)) << 4);           \
                uint32_t bhf[2], blf[2];                                         \
                ldm_x2(bhf, KVhiU + off);                                        \
                ldm_x2(blf, KVloU + off);                                        \
                mma16816(c0, qh[kk], bhf);                                       \
                mma16816(c0, qh[kk], blf);                                       \
                mma16816(c0, ql[kk], bhf);                                       \
            }                                                                    \
            const int col = ch * 64 + wid * 8 + c2;                              \
            float2 v;                                                            \
            v.x = c0[0] * 0.125f; v.y = c0[1] * 0.125f;                          \
            *(float2*)&S[r * SD + col] = v;                                      \
            v.x = c0[2] * 0.125f; v.y = c0[3] * 0.125f;                          \
            *(float2*)&S[(r + 8) * SD + col] = v;                                \
        }                                                                        \
    }

    // ---------------- variant 2 scores -> softmax -> attn2 ----------------
    stage64(smb, gK2h, gK2l, bh, 0, 0, tid);
    SCORE_PASS(gK2h, gK2l, gQ2h, gQ2l);

    // prefetch K1 chunk 0 during softmax
    stage64(smb, gK1h, gK1l, bh, 0, 0, tid);
    __syncthreads();

    // softmax attn2 (16 rows, 8 warps x 2 tasks); write global only
    for (int q = wid; q < 16; q += 8) {
        float* row = S + q * SD;
        float vreg[32];
        float m = -3.4e38f;
#pragma unroll
        for (int j = 0; j < 32; j++) {
            int k = lane + 32 * j;
            float v = row[k];
            if (padrow[k] == 0) v = -1e9f;
            vreg[j] = v;
            m = fmaxf(m, v);
        }
#pragma unroll
        for (int o = 16; o > 0; o >>= 1) m = fmaxf(m, __shfl_xor_sync(0xffffffffu, m, o));
        float s = 0.f;
#pragma unroll
        for (int j = 0; j < 32; j++) { vreg[j] = fexp(vreg[j] - m); s += vreg[j]; }
#pragma unroll
        for (int o = 16; o > 0; o >>= 1) s += __shfl_xor_sync(0xffffffffu, s, o);
        float rr = 1.0f / s;
        float* gout = attn2 + ((size_t)bh * 1024 + qbase + q) * 1024;
#pragma unroll
        for (int j = 0; j < 32; j++)
            gout[lane + 32 * j] = vreg[j] * rr;
    }
    __syncthreads();

    // ---------------- variant 1 scores -> softmax -> attn1 (+ keep in S) ----
    SCORE_PASS(gK1h, gK1l, gQ1h, gQ1l);

    // prefetch V chunk 0 during softmax
    stage64(smb, gVh, gVl, bh, 0, 0, tid);
    __syncthreads();

    for (int q = wid; q < 16; q += 8) {
        float* row = S + q * SD;
        float vreg[32];
        float m = -3.4e38f;
#pragma unroll
        for (int j = 0; j < 32; j++) {
            int k = lane + 32 * j;
            float v = row[k];
            if (padrow[k] == 0) v = -1e9f;
            vreg[j] = v;
            m = fmaxf(m, v);
        }
#pragma unroll
        for (int o = 16; o > 0; o >>= 1) m = fmaxf(m, __shfl_xor_sync(0xffffffffu, m, o));
        float s = 0.f;
#pragma unroll
        for (int j = 0; j < 32; j++) { vreg[j] = fexp(vreg[j] - m); s += vreg[j]; }
#pragma unroll
        for (int o = 16; o > 0; o >>= 1) s += __shfl_xor_sync(0xffffffffu, s, o);
        float rr = 1.0f / s;
        float* gout = attn1 + ((size_t)bh * 1024 + qbase + q) * 1024;
#pragma unroll
        for (int j = 0; j < 32; j++) {
            float e = vreg[j] * rr;
            row[lane + 32 * j] = e;
            gout[lane + 32 * j] = e;
        }
    }
    __syncthreads();

    // ---------------- combine: S <- C * (a1 - lam * attn2_global) ----------
    {
        const float lam = lamp[0];
        const float* a2g = attn2 + ((size_t)bh * 1024 + qbase) * 1024;
        const float* cg  = Cmask + ((size_t)b * 1024 + qbase) * 1024;
        for (int t = tid; t < 16384; t += 256) {
            int q = t >> 10, k = t & 1023;
            float a2 = a2g[(size_t)q * 1024 + k];
            float c  = cg [(size_t)q * 1024 + k];
            S[q * SD + k] = c * (S[q * SD + k] - lam * a2);
        }
    }
    __syncthreads();

    // ---------------- phase 2: ctx = P @ V, per-chunk P packing ------------
    {
        const uint32_t ua = (uint32_t)((((lane & 15) * 2 +
                             ((lane >> 4) ^ (((lane & 15) >> 2) & 1)))) << 4);
        float cacc[4] = {0.f, 0.f, 0.f, 0.f};
        for (int ch = 0; ch < 16; ch++) {
            const int buf = ch & 1;
            // pack P chunk (16q x 64k) into Pc[buf] hi/lo
            {
                uint32_t* Pchi = (uint32_t*)(smc + OFF_PC + buf * 4096u);
                uint32_t* Pclo = Pchi + 512;
#pragma unroll
                for (int i = 0; i < 2; i++) {
                    int pidx = tid + i * 256;          // 0..511
                    int q  = pidx >> 5;
                    int kp = pidx & 31;
                    int kl = kp * 2;
                    uint32_t hv, lv;
                    splitpair(S[q * SD + ch * 64 + kl], S[q * SD + ch * 64 + kl + 1],
                              hv, lv);
                    int kb16  = kl >> 4;
                    int colin = kl & 15;
                    int half  = colin >> 3;
                    int w     = (colin & 7) >> 1;
                    int u     = q * 2 + (half ^ ((q >> 2) & 1));
                    int addr  = kb16 * 128 + u * 4 + w;
                    Pchi[addr] = hv;
                    Pclo[addr] = lv;
                }
            }
            CPWAIT0;
            __syncthreads();
            if (ch < 15) stage64(smb, gVh, gVl, bh, ch + 1, buf ^ 1, tid);

            const uint32_t VhiU = smb + OFF_KV + buf * 16384u;
            const uint32_t VloU = VhiU + 8192u;
            const uint32_t PbU  = smb + OFF_PC + buf * 4096u;
#pragma unroll
            for (int k2 = 0; k2 < 2; k2++) {
                int lrow = k2 * 32 + (lane >> 3) * 8 + (lane & 7);
                uint32_t boff = lrow * 128 + ((wid ^ (lrow & 7)) << 4);
                uint32_t bhf[4], blf[4];
                ldm_x4_t(bhf, VhiU + boff);
                ldm_x4_t(blf, VloU + boff);
#pragma unroll
                for (int sub = 0; sub < 2; sub++) {
                    int kb16 = k2 * 2 + sub;
                    uint32_t ah[4], al[4];
                    ldm_x4(ah, PbU + kb16 * 512 + ua);
                    ldm_x4(al, PbU + 2048u + kb16 * 512 + ua);
                    mma16816(cacc, ah, &bhf[sub * 2]);
                    mma16816(cacc, ah, &blf[sub * 2]);
                    mma16816(cacc, al, &bhf[sub * 2]);
                }
            }
            __syncthreads();
        }
        size_t base = ((size_t)(b * 1024 + qbase + r)) * 1024 + h * 64 + wid * 8 + c2;
        float2 v0; v0.x = cacc[0]; v0.y = cacc[1];
        float2 v1; v1.x = cacc[2]; v1.y = cacc[3];
        *(float2*)&gCtx[base]            = v0;
        *(float2*)&gCtx[base + 8 * 1024] = v1;
    }
#undef SCORE_PASS
}

// ---------------------------------------------------------------------------
// stats_kernel: GroupNorm stats -> folded per-(b,d) scale/bias
// ---------------------------------------------------------------------------
__global__ void stats_kernel(const float* __restrict__ gnw,
                             const float* __restrict__ gnb)
{
    const int bh = blockIdx.x;
    const int b = bh >> 4, h = bh & 15;
    const int tid = threadIdx.x;
    __shared__ float rs[256], rq[256];
    float s = 0.f, sq = 0.f;
    for (int t = tid; t < 65536; t += 256) {
        int srow = t >> 6, d = t & 63;
        float x = gCtx[((size_t)b * 1024 + srow) * 1024 + h * 64 + d];
        s += x; sq += x * x;
    }
    rs[tid] = s; rq[tid] = sq;
    __syncthreads();
    for (int o = 128; o > 0; o >>= 1) {
        if (tid < o) { rs[tid] += rs[tid + o]; rq[tid] += rq[tid + o]; }
        __syncthreads();
    }
    if (tid < 64) {
        float mean = rs[0] * (1.0f / 65536.0f);
        float var  = rq[0] * (1.0f / 65536.0f) - mean * mean;
        float rstd = rsqrtf(var + 1e-5f);
        int d = h * 64 + tid;
        float w = gnw[d];
        float scl = rstd * w * 0.19999999999999996f;
        gScaleArr[b * 1024 + d] = scl;
        gBiasArr [b * 1024 + d] = (gnb[d] - mean * rstd * w) * 0.19999999999999996f;
    }
}

// ---------------------------------------------------------------------------
// Launch
// ---------------------------------------------------------------------------
extern "C" void kernel_launch(void* const* d_in, const int* in_sizes, int n_in,
                              void* d_out, int out_size)
{
    const float* x    = (const float*)d_in[0];
    const float* lam  = (const float*)d_in[1];
    const float* C    = (const float*)d_in[2];
    const int*   pad  = (const int*)  d_in[3];
    const float* wq   = (const float*)d_in[4];
    const float* wqb  = (const float*)d_in[5];
    const float* wk   = (const float*)d_in[6];
    const float* wkb  = (const float*)d_in[7];
    const float* wv   = (const float*)d_in[8];
    const float* wvb  = (const float*)d_in[9];
    const float* wo   = (const float*)d_in[10];
    const float* wob  = (const float*)d_in[11];
    const float* gnw  = (const float*)d_in[12];
    const float* gnb  = (const float*)d_in[13];

    float* out   = (float*)d_out;
    float* attn1 = out + (size_t)BB * SS * DD;
    float* attn2 = attn1 + (size_t)BB * HH * SS * SS;

    cudaFuncSetAttribute(attn_kernel, cudaFuncAttributeMaxDynamicSharedMemorySize,
                         ATTN_SMEM);
    cudaFuncSetAttribute(mma_gemm<0>, cudaFuncAttributeMaxDynamicSharedMemorySize, 65536);
    cudaFuncSetAttribute(mma_gemm<1>, cudaFuncAttributeMaxDynamicSharedMemorySize, 65536);

    prep_split<<<512, 256>>>(x,  0, 2097152);
    prep_split<<<512, 256>>>(wq, 1, 1048576);
    prep_split<<<512, 256>>>(wk, 2, 1048576);
    prep_split<<<512, 256>>>(wv, 3, 524288);
    prep_split<<<512, 256>>>(wo, 4, 524288);

    mma_gemm<0><<<dim3(40, 32), 256, 65536>>>(wqb, wkb, wvb, nullptr, nullptr);
    attn_kernel<<<dim3(64, 16, 4), 256, ATTN_SMEM>>>(C, pad, lam, attn1, attn2);
    stats_kernel<<<64, 256>>>(gnw, gnb);
    prep_ctx<<<512, 256>>>();
    mma_gemm<1><<<dim3(8, 32), 256, 65536>>>(nullptr, nullptr, nullptr, wob, out);
}

// round 7
// speedup vs baseline: 2.7516x; 1.0353x over previous
#include <cuda_runtime.h>
#include <cuda_bf16.h>
#include <cstdint>

// Problem constants
#define BB 4
#define SS 1024
#define DD 1024
#define HH 16
#define DH 64

// ===========================================================================
// Packed bf16 hi/lo device globals (uint32 = bf16x2 pair along k/dh)
// ===========================================================================
__device__ __align__(16) uint32_t gXh[2097152],  gXl[2097152];   // x      [4096][512]
__device__ __align__(16) uint32_t gWh[2621440],  gWl[2621440];   // wq|wk|wv [5120][512]
__device__ __align__(16) uint32_t gWoh[524288],  gWol[524288];   // wo     [1024][512]
__device__ __align__(16) uint32_t gAh[2097152],  gAl[2097152];   // normalized ctx
__device__ __align__(16) uint32_t gQ1h[2097152], gQ1l[2097152];
__device__ __align__(16) uint32_t gQ2h[2097152], gQ2l[2097152];
__device__ __align__(16) uint32_t gK1h[2097152], gK1l[2097152];
__device__ __align__(16) uint32_t gK2h[2097152], gK2l[2097152];
__device__ __align__(16) uint32_t gVh [2097152], gVl [2097152];
__device__ float gCtx[4194304];
__device__ float gScaleArr[4096];
__device__ float gBiasArr [4096];

// ===========================================================================
// helpers
// ===========================================================================
static __device__ __forceinline__ uint32_t smem_u32(const void* p) {
    uint32_t a;
    asm("{ .reg .u64 t; cvta.to.shared.u64 t, %1; cvt.u32.u64 %0, t; }"
        : "=r"(a) : "l"(p));
    return a;
}
static __device__ __forceinline__ void ldm_x4(uint32_t* r, uint32_t addr) {
    asm volatile("ldmatrix.sync.aligned.m8n8.x4.shared.b16 {%0,%1,%2,%3}, [%4];"
                 : "=r"(r[0]), "=r"(r[1]), "=r"(r[2]), "=r"(r[3]) : "r"(addr));
}
static __device__ __forceinline__ void ldm_x2(uint32_t* r, uint32_t addr) {
    asm volatile("ldmatrix.sync.aligned.m8n8.x2.shared.b16 {%0,%1}, [%2];"
                 : "=r"(r[0]), "=r"(r[1]) : "r"(addr));
}
static __device__ __forceinline__ void ldm_x4_t(uint32_t* r, uint32_t addr) {
    asm volatile("ldmatrix.sync.aligned.m8n8.x4.trans.shared.b16 {%0,%1,%2,%3}, [%4];"
                 : "=r"(r[0]), "=r"(r[1]), "=r"(r[2]), "=r"(r[3]) : "r"(addr));
}
static __device__ __forceinline__ void mma16816(float* c, const uint32_t* a,
                                                const uint32_t* b) {
    asm volatile(
        "mma.sync.aligned.m16n8k16.row.col.f32.bf16.bf16.f32 "
        "{%0,%1,%2,%3}, {%4,%5,%6,%7}, {%8,%9}, {%0,%1,%2,%3};"
        : "+f"(c[0]), "+f"(c[1]), "+f"(c[2]), "+f"(c[3])
        : "r"(a[0]), "r"(a[1]), "r"(a[2]), "r"(a[3]), "r"(b[0]), "r"(b[1]));
}
static __device__ __forceinline__ void splitpair(float f0, float f1,
                                                 uint32_t& h, uint32_t& l) {
    __nv_bfloat16 h0 = __float2bfloat16(f0);
    __nv_bfloat16 h1 = __float2bfloat16(f1);
    __nv_bfloat16 l0 = __float2bfloat16(f0 - __bfloat162float(h0));
    __nv_bfloat16 l1 = __float2bfloat16(f1 - __bfloat162float(h1));
    __nv_bfloat162 hp; hp.x = h0; hp.y = h1;
    __nv_bfloat162 lp; lp.x = l0; lp.y = l1;
    h = *reinterpret_cast<uint32_t*>(&hp);
    l = *reinterpret_cast<uint32_t*>(&lp);
}
// fast exp on the FMA pipe
static __device__ __forceinline__ float fexp(float x) {
    float t = x * 1.4426950408889634f;
    t = fmaxf(t, -126.0f);
    float fl = floorf(t);
    float f = t - fl;
    float p = 1.33335581e-3f;
    p = fmaf(p, f, 9.61812910e-3f);
    p = fmaf(p, f, 5.55041087e-2f);
    p = fmaf(p, f, 2.40226507e-1f);
    p = fmaf(p, f, 6.93147180e-1f);
    p = fmaf(p, f, 1.0f);
    return p * __int_as_float(((int)fl + 127) << 23);
}
static __device__ __forceinline__ uint32_t sw_off(int row, int chunk) {
    return (uint32_t)(row * 64 + ((chunk ^ ((row >> 1) & 3)) << 4));
}
#define CPA16(dst, src) \
    asm volatile("cp.async.cg.shared.global [%0], [%1], 16;" :: "r"(dst), "l"(src))
#define CPCOMMIT asm volatile("cp.async.commit_group;" ::: "memory")
#define CPWAIT1  asm volatile("cp.async.wait_group 1;" ::: "memory")
#define CPWAIT0  asm volatile("cp.async.wait_group 0;" ::: "memory")

// ===========================================================================
// prep kernels
// ===========================================================================
__global__ void prep_split(const float* __restrict__ src, int which, int npairs)
{
    uint32_t* dh; uint32_t* dl;
    switch (which) {
        case 0: dh = gXh;           dl = gXl;           break;
        case 1: dh = gWh;           dl = gWl;           break;
        case 2: dh = gWh + 1048576; dl = gWl + 1048576; break;
        case 3: dh = gWh + 2097152; dl = gWl + 2097152; break;
        default: dh = gWoh;         dl = gWol;          break;
    }
    int i = blockIdx.x * blockDim.x + threadIdx.x;
    int stride = gridDim.x * blockDim.x;
    for (; i < npairs; i += stride) {
        float2 v = *(const float2*)(src + 2 * (size_t)i);
        uint32_t h, l;
        splitpair(v.x, v.y, h, l);
        dh[i] = h; dl[i] = l;
    }
}

__global__ void prep_ctx()
{
    int i = blockIdx.x * blockDim.x + threadIdx.x;
    int stride = gridDim.x * blockDim.x;
    for (; i < 2097152; i += stride) {
        int m = i >> 9, kp = i & 511, b = m >> 10;
        float2 v  = *(const float2*)&gCtx[(size_t)m * 1024 + 2 * kp];
        float2 sc = *(const float2*)&gScaleArr[b * 1024 + 2 * kp];
        float2 bi = *(const float2*)&gBiasArr [b * 1024 + 2 * kp];
        uint32_t h, l;
        splitpair(v.x * sc.x + bi.x, v.y * sc.y + bi.y, h, l);
        gAh[i] = h; gAl[i] = l;
    }
}

// ===========================================================================
// mma_gemm<MODE>: pure bf16 GEMM, 128x128 tile, BK=32,
// 3-stage circular cp.async pipeline, ONE __syncthreads per chunk.
// smem: 3 buffers x (Ahi 8K | Alo 8K | Bhi 8K | Blo 8K) = 96KB dynamic.
// ===========================================================================
template<int MODE>
__global__ __launch_bounds__(256, 2)
void mma_gemm(const float* __restrict__ wqb, const float* __restrict__ wkb,
              const float* __restrict__ wvb, const float* __restrict__ ob,
              float* __restrict__ out)
{
    extern __shared__ char sm[];
    const uint32_t smb = smem_u32(sm);
    const int tid  = threadIdx.x;
    const int lane = tid & 31;
    const int warp = tid >> 5;
    const int wm   = warp >> 1;
    const int wn   = warp & 1;
    const int n0 = blockIdx.x * 128;
    const int m0 = blockIdx.y * 128;
    const int b  = m0 >> 10;

    const uint32_t* Ah = (MODE == 0) ? gXh : gAh;
    const uint32_t* Al = (MODE == 0) ? gXl : gAl;
    const uint32_t* Bh = (MODE == 0) ? gWh : gWoh;
    const uint32_t* Bl = (MODE == 0) ? gWl : gWol;
    const float* Wb;
    if (MODE == 0) {
        if (n0 < 2048)      Wb = wqb + n0;
        else if (n0 < 4096) Wb = wkb + (n0 - 2048);
        else                Wb = wvb + (n0 - 4096);
    } else {
        Wb = ob + n0;
    }

    float acc[2][8][4];
#pragma unroll
    for (int i = 0; i < 2; i++)
#pragma unroll
        for (int j = 0; j < 8; j++)
#pragma unroll
            for (int v = 0; v < 4; v++) acc[i][j][v] = 0.f;

#define STAGE_GEMM(c, buf)                                                        \
    {                                                                             \
        _Pragma("unroll")                                                         \
        for (int i = 0; i < 8; i++) {                                             \
            int t = tid + i * 256;                                                \
            int tile = t >> 9;                                                    \
            int r = (t >> 2) & 127;                                               \
            int u = t & 3;                                                        \
            uint32_t dst = smb + (uint32_t)(buf) * 32768u + tile * 8192u          \
                           + sw_off(r, u);                                        \
            const uint32_t* sa = (tile == 0) ? Ah : (tile == 1) ? Al              \
                                : (tile == 2) ? Bh : Bl;                          \
            const uint32_t* src = sa + (size_t)((tile < 2 ? m0 : n0) + r) * 512   \
                                   + (c) * 16 + u * 4;                            \
            CPA16(dst, src);                                                      \
        }                                                                         \
        CPCOMMIT;                                                                 \
    }

    STAGE_GEMM(0, 0);
    STAGE_GEMM(1, 1);
    int bufc = 0;   // (c % 3)
    for (int c = 0; c < 32; c++) {
        if (c < 30) { CPWAIT1; } else { CPWAIT0; }
        __syncthreads();
        if (c < 30) {
            int nb = bufc + 2; if (nb >= 3) nb -= 3;
            STAGE_GEMM(c + 2, nb);
        }

        const uint32_t base = smb + (uint32_t)bufc * 32768u;
        const uint32_t AhiU = base, AloU = base + 8192u;
        const uint32_t BhiU = base + 16384u, BloU = base + 24576u;
#pragma unroll
        for (int kk = 0; kk < 2; kk++) {
            uint32_t ah[2][4], al[2][4];
            const int arow = wm * 32 + (lane & 7) + (((lane >> 3) & 1) << 3);
            const int achunk = kk * 2 + (lane >> 4);
#pragma unroll
            for (int mi = 0; mi < 2; mi++) {
                uint32_t off = sw_off(arow + mi * 16, achunk);
                ldm_x4(ah[mi], AhiU + off);
                ldm_x4(al[mi], AloU + off);
            }
            const int brow0 = wn * 64 + (lane & 7) + ((lane >> 4) << 3);
            const int bchunk = kk * 2 + ((lane >> 3) & 1);
#pragma unroll
            for (int half = 0; half < 2; half++) {
                uint32_t bhf[2][4], blf[2][4];
#pragma unroll
                for (int j = 0; j < 2; j++) {
                    uint32_t off = sw_off(brow0 + half * 32 + j * 16, bchunk);
                    ldm_x4(bhf[j], BhiU + off);
                    ldm_x4(blf[j], BloU + off);
                }
#pragma unroll
                for (int mi = 0; mi < 2; mi++)
#pragma unroll
                    for (int j = 0; j < 2; j++)
#pragma unroll
                        for (int s = 0; s < 2; s++) {
                            float* cp = acc[mi][half * 4 + j * 2 + s];
                            mma16816(cp, ah[mi], &bhf[j][s * 2]);
                            mma16816(cp, ah[mi], &blf[j][s * 2]);
                            mma16816(cp, al[mi], &bhf[j][s * 2]);
                        }
            }
        }
        bufc++; if (bufc >= 3) bufc -= 3;
    }
#undef STAGE_GEMM

    if (MODE == 0) {
        const int sect = n0 >> 10;
        uint32_t* dstH = (sect == 0) ? gQ1h : (sect == 1) ? gQ2h :
                         (sect == 2) ? gK1h : (sect == 3) ? gK2h : gVh;
        uint32_t* dstL = (sect == 0) ? gQ1l : (sect == 1) ? gQ2l :
                         (sect == 2) ? gK1l : (sect == 3) ? gK2l : gVl;
#pragma unroll
        for (int mi = 0; mi < 2; mi++) {
            int m = m0 + wm * 32 + mi * 16 + (lane >> 2);
            int s = m & 1023;
#pragma unroll
            for (int nh = 0; nh < 8; nh++) {
                int nl = wn * 64 + nh * 8 + 2 * (lane & 3);
                int nn = (n0 & 1023) + nl;
                int h = nn >> 6, dh = nn & 63;
                float b0 = Wb[nl], b1 = Wb[nl + 1];
                uint32_t h0, l0, h1, l1;
                splitpair(acc[mi][nh][0] + b0, acc[mi][nh][1] + b1, h0, l0);
                splitpair(acc[mi][nh][2] + b0, acc[mi][nh][3] + b1, h1, l1);
                size_t base = ((size_t)((b << 4) + h) * 1024 + s) * 32 + (dh >> 1);
                dstH[base] = h0; dstL[base] = l0;
                dstH[base + 256] = h1; dstL[base + 256] = l1;
            }
        }
    } else {
#pragma unroll
        for (int mi = 0; mi < 2; mi++) {
            int m = m0 + wm * 32 + mi * 16 + (lane >> 2);
#pragma unroll
            for (int nh = 0; nh < 8; nh++) {
                int nl = wn * 64 + nh * 8 + 2 * (lane & 3);
                float b0 = Wb[nl], b1 = Wb[nl + 1];
                float2 v0; v0.x = acc[mi][nh][0] + b0; v0.y = acc[mi][nh][1] + b1;
                float2 v1; v1.x = acc[mi][nh][2] + b0; v1.y = acc[mi][nh][3] + b1;
                *(float2*)&out[(size_t)m * 1024 + n0 + nl]       = v0;
                *(float2*)&out[(size_t)(m + 8) * 1024 + n0 + nl] = v1;
            }
        }
    }
}

// ===========================================================================
// attn_kernel: variant-sequential, 107KB smem -> 2 CTAs/SM.
// smem: S fp32[16][1032] (66048) | KV stage 2x16KB (32768) | Pc 2x4KB (8192)
// ===========================================================================
#define SD 1032
#define OFF_KV 66048u
#define OFF_PC 98816u
#define ATTN_SMEM 107008

// stage 64 keys (hi+lo) of a packed [bh][1024][32-u32] tensor into buf
static __device__ __forceinline__ void stage64(uint32_t smb, const uint32_t* sH,
                                               const uint32_t* sL, int bh,
                                               int ch64, int buf, int tid)
{
#pragma unroll
    for (int i = 0; i < 4; i++) {
        int t = tid + i * 256;            // 0..1023
        int tile = t >> 9;                // 0 = hi, 1 = lo
        int row = (t >> 3) & 63;
        int cu = t & 7;
        uint32_t dst = smb + OFF_KV + buf * 16384u + tile * 8192u +
                       row * 128u + (uint32_t)((cu ^ (row & 7)) << 4);
        const uint32_t* src = (tile ? sL : sH) +
                              ((size_t)bh * 1024 + ch64 * 64 + row) * 32 + cu * 4;
        CPA16(dst, src);
    }
    CPCOMMIT;
}

__global__ __launch_bounds__(256, 2)
void attn_kernel(const float* __restrict__ Cmask,
                 const int*   __restrict__ pad,
                 const float* __restrict__ lamp,
                 float* __restrict__ attn1,
                 float* __restrict__ attn2)
{
    extern __shared__ char smc[];
    const uint32_t smb = smem_u32(smc);
    float* S = (float*)smc;

    const int qt = blockIdx.x;
    const int h  = blockIdx.y;
    const int b  = blockIdx.z;
    const int tid  = threadIdx.x;
    const int wid  = tid >> 5;
    const int lane = tid & 31;
    const int bh = b * 16 + h;
    const int qbase = qt * 16;
    const int r  = lane >> 2;
    const int c2 = (lane & 3) * 2;
    const int* padrow = pad + b * 1024;

    // ---------------- score pass (one variant) ----------------
#define SCORE_PASS(KH, KL, QH, QL)                                               \
    {                                                                            \
        uint32_t qh[4][4], ql[4][4];                                             \
        {                                                                        \
            size_t qb0 = ((size_t)bh * 1024 + qbase + r) * 32;                   \
            size_t qb1 = qb0 + 8 * 32;                                           \
            _Pragma("unroll")                                                    \
            for (int kk = 0; kk < 4; kk++) {                                     \
                int p = kk * 8 + (lane & 3);                                     \
                qh[kk][0] = QH[qb0 + p];     ql[kk][0] = QL[qb0 + p];            \
                qh[kk][1] = QH[qb1 + p];     ql[kk][1] = QL[qb1 + p];            \
                qh[kk][2] = QH[qb0 + p + 4]; ql[kk][2] = QL[qb0 + p + 4];        \
                qh[kk][3] = QH[qb1 + p + 4]; ql[kk][3] = QL[qb1 + p + 4];        \
            }                                                                    \
        }                                                                        \
        for (int ch = 0; ch < 16; ch++) {                                        \
            CPWAIT0;                                                             \
            __syncthreads();                                                     \
            if (ch < 15) stage64(smb, KH, KL, bh, ch + 1, (ch + 1) & 1, tid);    \
            const uint32_t KVhiU = smb + OFF_KV + (ch & 1) * 16384u;             \
            const uint32_t KVloU = KVhiU + 8192u;                                \
            float c0[4] = {0.f, 0.f, 0.f, 0.f};                                  \
            const int brow = wid * 8 + (lane & 7);                               \
            _Pragma("unroll")                                                    \
            for (int kk = 0; kk < 4; kk++) {                                     \
                int bch = kk * 2 + ((lane >> 3) & 1);                            \
                uint32_t off = brow * 128 + ((bch ^ (brow & 7)) << 4);           \
                uint32_t bhf[2], blf[2];                                         \
                ldm_x2(bhf, KVhiU + off);                                        \
                ldm_x2(blf, KVloU + off);                                        \
                mma16816(c0, qh[kk], bhf);                                       \
                mma16816(c0, qh[kk], blf);                                       \
                mma16816(c0, ql[kk], bhf);                                       \
            }                                                                    \
            const int col = ch * 64 + wid * 8 + c2;                              \
            float2 v;                                                            \
            v.x = c0[0] * 0.125f; v.y = c0[1] * 0.125f;                          \
            *(float2*)&S[r * SD + col] = v;                                      \
            v.x = c0[2] * 0.125f; v.y = c0[3] * 0.125f;                          \
            *(float2*)&S[(r + 8) * SD + col] = v;                                \
        }                                                                        \
    }

    // ---------------- variant 2 scores -> softmax -> attn2 ----------------
    stage64(smb, gK2h, gK2l, bh, 0, 0, tid);
    SCORE_PASS(gK2h, gK2l, gQ2h, gQ2l);

    // prefetch K1 chunk 0 during softmax
    stage64(smb, gK1h, gK1l, bh, 0, 0, tid);
    __syncthreads();

    // softmax attn2 (16 rows, 8 warps x 2 tasks); write global only
    for (int q = wid; q < 16; q += 8) {
        float* row = S + q * SD;
        float vreg[32];
        float m = -3.4e38f;
#pragma unroll
        for (int j = 0; j < 32; j++) {
            int k = lane + 32 * j;
            float v = row[k];
            if (padrow[k] == 0) v = -1e9f;
            vreg[j] = v;
            m = fmaxf(m, v);
        }
#pragma unroll
        for (int o = 16; o > 0; o >>= 1) m = fmaxf(m, __shfl_xor_sync(0xffffffffu, m, o));
        float s = 0.f;
#pragma unroll
        for (int j = 0; j < 32; j++) { vreg[j] = fexp(vreg[j] - m); s += vreg[j]; }
#pragma unroll
        for (int o = 16; o > 0; o >>= 1) s += __shfl_xor_sync(0xffffffffu, s, o);
        float rr = 1.0f / s;
        float* gout = attn2 + ((size_t)bh * 1024 + qbase + q) * 1024;
#pragma unroll
        for (int j = 0; j < 32; j++)
            gout[lane + 32 * j] = vreg[j] * rr;
    }
    __syncthreads();

    // ---------------- variant 1 scores -> softmax+combine -> attn1 & P in S -
    SCORE_PASS(gK1h, gK1l, gQ1h, gQ1l);

    // prefetch V chunk 0 during softmax
    stage64(smb, gVh, gVl, bh, 0, 0, tid);
    __syncthreads();

    {
        const float lam = lamp[0];
        for (int q = wid; q < 16; q += 8) {
            float* row = S + q * SD;
            float vreg[32];
            float m = -3.4e38f;
#pragma unroll
            for (int j = 0; j < 32; j++) {
                int k = lane + 32 * j;
                float v = row[k];
                if (padrow[k] == 0) v = -1e9f;
                vreg[j] = v;
                m = fmaxf(m, v);
            }
#pragma unroll
            for (int o = 16; o > 0; o >>= 1) m = fmaxf(m, __shfl_xor_sync(0xffffffffu, m, o));
            float s = 0.f;
#pragma unroll
            for (int j = 0; j < 32; j++) { vreg[j] = fexp(vreg[j] - m); s += vreg[j]; }
#pragma unroll
            for (int o = 16; o > 0; o >>= 1) s += __shfl_xor_sync(0xffffffffu, s, o);
            float rr = 1.0f / s;
            float* gout = attn1 + ((size_t)bh * 1024 + qbase + q) * 1024;
            const float* a2g = attn2 + ((size_t)bh * 1024 + qbase + q) * 1024;
            const float* cg  = Cmask + ((size_t)b * 1024 + qbase + q) * 1024;
            // fused: write attn1, and S <- C * (a1 - lam * a2)
#pragma unroll
            for (int j = 0; j < 32; j++) {
                int k = lane + 32 * j;
                float e = vreg[j] * rr;
                gout[k] = e;
                row[k] = cg[k] * (e - lam * a2g[k]);
            }
        }
    }
    __syncthreads();

    // ---------------- phase 2: ctx = P @ V, per-chunk P packing ------------
    {
        const uint32_t ua = (uint32_t)((((lane & 15) * 2 +
                             ((lane >> 4) ^ (((lane & 15) >> 2) & 1)))) << 4);
        float cacc[4] = {0.f, 0.f, 0.f, 0.f};
        for (int ch = 0; ch < 16; ch++) {
            const int buf = ch & 1;
            // pack P chunk (16q x 64k) into Pc[buf] hi/lo
            {
                uint32_t* Pchi = (uint32_t*)(smc + OFF_PC + buf * 4096u);
                uint32_t* Pclo = Pchi + 512;
#pragma unroll
                for (int i = 0; i < 2; i++) {
                    int pidx = tid + i * 256;          // 0..511
                    int q  = pidx >> 5;
                    int kp = pidx & 31;
                    int kl = kp * 2;
                    uint32_t hv, lv;
                    splitpair(S[q * SD + ch * 64 + kl], S[q * SD + ch * 64 + kl + 1],
                              hv, lv);
                    int kb16  = kl >> 4;
                    int colin = kl & 15;
                    int half  = colin >> 3;
                    int w     = (colin & 7) >> 1;
                    int u     = q * 2 + (half ^ ((q >> 2) & 1));
                    int addr  = kb16 * 128 + u * 4 + w;
                    Pchi[addr] = hv;
                    Pclo[addr] = lv;
                }
            }
            CPWAIT0;
            __syncthreads();
            if (ch < 15) stage64(smb, gVh, gVl, bh, ch + 1, buf ^ 1, tid);

            const uint32_t VhiU = smb + OFF_KV + buf * 16384u;
            const uint32_t VloU = VhiU + 8192u;
            const uint32_t PbU  = smb + OFF_PC + buf * 4096u;
#pragma unroll
            for (int k2 = 0; k2 < 2; k2++) {
                int lrow = k2 * 32 + (lane >> 3) * 8 + (lane & 7);
                uint32_t boff = lrow * 128 + ((wid ^ (lrow & 7)) << 4);
                uint32_t bhf[4], blf[4];
                ldm_x4_t(bhf, VhiU + boff);
                ldm_x4_t(blf, VloU + boff);
#pragma unroll
                for (int sub = 0; sub < 2; sub++) {
                    int kb16 = k2 * 2 + sub;
                    uint32_t ah[4], al[4];
                    ldm_x4(ah, PbU + kb16 * 512 + ua);
                    ldm_x4(al, PbU + 2048u + kb16 * 512 + ua);
                    mma16816(cacc, ah, &bhf[sub * 2]);
                    mma16816(cacc, ah, &blf[sub * 2]);
                    mma16816(cacc, al, &bhf[sub * 2]);
                }
            }
            __syncthreads();
        }
        size_t base = ((size_t)(b * 1024 + qbase + r)) * 1024 + h * 64 + wid * 8 + c2;
        float2 v0; v0.x = cacc[0]; v0.y = cacc[1];
        float2 v1; v1.x = cacc[2]; v1.y = cacc[3];
        *(float2*)&gCtx[base]            = v0;
        *(float2*)&gCtx[base + 8 * 1024] = v1;
    }
#undef SCORE_PASS
}

// ---------------------------------------------------------------------------
// stats_kernel: GroupNorm stats -> folded per-(b,d) scale/bias
// ---------------------------------------------------------------------------
__global__ void stats_kernel(const float* __restrict__ gnw,
                             const float* __restrict__ gnb)
{
    const int bh = blockIdx.x;
    const int b = bh >> 4, h = bh & 15;
    const int tid = threadIdx.x;
    __shared__ float rs[256], rq[256];
    float s = 0.f, sq = 0.f;
    for (int t = tid; t < 65536; t += 256) {
        int srow = t >> 6, d = t & 63;
        float x = gCtx[((size_t)b * 1024 + srow) * 1024 + h * 64 + d];
        s += x; sq += x * x;
    }
    rs[tid] = s; rq[tid] = sq;
    __syncthreads();
    for (int o = 128; o > 0; o >>= 1) {
        if (tid < o) { rs[tid] += rs[tid + o]; rq[tid] += rq[tid + o]; }
        __syncthreads();
    }
    if (tid < 64) {
        float mean = rs[0] * (1.0f / 65536.0f);
        float var  = rq[0] * (1.0f / 65536.0f) - mean * mean;
        float rstd = rsqrtf(var + 1e-5f);
        int d = h * 64 + tid;
        float w = gnw[d];
        float scl = rstd * w * 0.19999999999999996f;
        gScaleArr[b * 1024 + d] = scl;
        gBiasArr [b * 1024 + d] = (gnb[d] - mean * rstd * w) * 0.19999999999999996f;
    }
}

// ---------------------------------------------------------------------------
// Launch
// ---------------------------------------------------------------------------
extern "C" void kernel_launch(void* const* d_in, const int* in_sizes, int n_in,
                              void* d_out, int out_size)
{
    const float* x    = (const float*)d_in[0];
    const float* lam  = (const float*)d_in[1];
    const float* C    = (const float*)d_in[2];
    const int*   pad  = (const int*)  d_in[3];
    const float* wq   = (const float*)d_in[4];
    const float* wqb  = (const float*)d_in[5];
    const float* wk   = (const float*)d_in[6];
    const float* wkb  = (const float*)d_in[7];
    const float* wv   = (const float*)d_in[8];
    const float* wvb  = (const float*)d_in[9];
    const float* wo   = (const float*)d_in[10];
    const float* wob  = (const float*)d_in[11];
    const float* gnw  = (const float*)d_in[12];
    const float* gnb  = (const float*)d_in[13];

    float* out   = (float*)d_out;
    float* attn1 = out + (size_t)BB * SS * DD;
    float* attn2 = attn1 + (size_t)BB * HH * SS * SS;

    cudaFuncSetAttribute(attn_kernel, cudaFuncAttributeMaxDynamicSharedMemorySize,
                         ATTN_SMEM);
    cudaFuncSetAttribute(mma_gemm<0>, cudaFuncAttributeMaxDynamicSharedMemorySize, 98304);
    cudaFuncSetAttribute(mma_gemm<1>, cudaFuncAttributeMaxDynamicSharedMemorySize, 98304);

    prep_split<<<512, 256>>>(x,  0, 2097152);
    prep_split<<<512, 256>>>(wq, 1, 1048576);
    prep_split<<<512, 256>>>(wk, 2, 1048576);
    prep_split<<<512, 256>>>(wv, 3, 524288);
    prep_split<<<512, 256>>>(wo, 4, 524288);

    mma_gemm<0><<<dim3(40, 32), 256, 98304>>>(wqb, wkb, wvb, nullptr, nullptr);
    attn_kernel<<<dim3(64, 16, 4), 256, ATTN_SMEM>>>(C, pad, lam, attn1, attn2);
    stats_kernel<<<64, 256>>>(gnw, gnb);
    prep_ctx<<<512, 256>>>();
    mma_gemm<1><<<dim3(8, 32), 256, 98304>>>(nullptr, nullptr, nullptr, wob, out);
}

// round 8
// speedup vs baseline: 3.2464x; 1.1798x over previous
#include <cuda_runtime.h>
#include <cuda_fp16.h>
#include <cstdint>

// Problem constants
#define BB 4
#define SS 1024
#define DD 1024
#define HH 16
#define DH 64

// ===========================================================================
// Packed fp16 device globals (uint32 = half2 pair along k/dh)
// A-side operands: hi only.  B-side operands: hi + lo.
// ===========================================================================
__device__ __align__(16) uint32_t gXh[2097152];                  // x      [4096][512]
__device__ __align__(16) uint32_t gWh[2621440],  gWl[2621440];   // wq|wk|wv [5120][512]
__device__ __align__(16) uint32_t gWoh[524288],  gWol[524288];   // wo     [1024][512]
__device__ __align__(16) uint32_t gAh[2097152];                  // normalized ctx
__device__ __align__(16) uint32_t gQ1h[2097152];
__device__ __align__(16) uint32_t gQ2h[2097152];
__device__ __align__(16) uint32_t gK1h[2097152], gK1l[2097152];
__device__ __align__(16) uint32_t gK2h[2097152], gK2l[2097152];
__device__ __align__(16) uint32_t gVh [2097152], gVl [2097152];
__device__ float gCtx[4194304];
__device__ float gScaleArr[4096];
__device__ float gBiasArr [4096];

// ===========================================================================
// helpers
// ===========================================================================
static __device__ __forceinline__ uint32_t smem_u32(const void* p) {
    uint32_t a;
    asm("{ .reg .u64 t; cvta.to.shared.u64 t, %1; cvt.u32.u64 %0, t; }"
        : "=r"(a) : "l"(p));
    return a;
}
static __device__ __forceinline__ void ldm_x4(uint32_t* r, uint32_t addr) {
    asm volatile("ldmatrix.sync.aligned.m8n8.x4.shared.b16 {%0,%1,%2,%3}, [%4];"
                 : "=r"(r[0]), "=r"(r[1]), "=r"(r[2]), "=r"(r[3]) : "r"(addr));
}
static __device__ __forceinline__ void ldm_x2(uint32_t* r, uint32_t addr) {
    asm volatile("ldmatrix.sync.aligned.m8n8.x2.shared.b16 {%0,%1}, [%2];"
                 : "=r"(r[0]), "=r"(r[1]) : "r"(addr));
}
static __device__ __forceinline__ void ldm_x4_t(uint32_t* r, uint32_t addr) {
    asm volatile("ldmatrix.sync.aligned.m8n8.x4.trans.shared.b16 {%0,%1,%2,%3}, [%4];"
                 : "=r"(r[0]), "=r"(r[1]), "=r"(r[2]), "=r"(r[3]) : "r"(addr));
}
// fp16 mma, fp32 accumulate
static __device__ __forceinline__ void mma16816(float* c, const uint32_t* a,
                                                const uint32_t* b) {
    asm volatile(
        "mma.sync.aligned.m16n8k16.row.col.f32.f16.f16.f32 "
        "{%0,%1,%2,%3}, {%4,%5,%6,%7}, {%8,%9}, {%0,%1,%2,%3};"
        : "+f"(c[0]), "+f"(c[1]), "+f"(c[2]), "+f"(c[3])
        : "r"(a[0]), "r"(a[1]), "r"(a[2]), "r"(a[3]), "r"(b[0]), "r"(b[1]));
}
static __device__ __forceinline__ uint32_t pack2h(float f0, float f1) {
    __half2 hp; hp.x = __float2half_rn(f0); hp.y = __float2half_rn(f1);
    return *reinterpret_cast<uint32_t*>(&hp);
}
static __device__ __forceinline__ void splitpair(float f0, float f1,
                                                 uint32_t& h, uint32_t& l) {
    __half h0 = __float2half_rn(f0);
    __half h1 = __float2half_rn(f1);
    __half2 hp; hp.x = h0; hp.y = h1;
    __half2 lp;
    lp.x = __float2half_rn(f0 - __half2float(h0));
    lp.y = __float2half_rn(f1 - __half2float(h1));
    h = *reinterpret_cast<uint32_t*>(&hp);
    l = *reinterpret_cast<uint32_t*>(&lp);
}
// fast exp on the FMA pipe
static __device__ __forceinline__ float fexp(float x) {
    float t = x * 1.4426950408889634f;
    t = fmaxf(t, -126.0f);
    float fl = floorf(t);
    float f = t - fl;
    float p = 1.33335581e-3f;
    p = fmaf(p, f, 9.61812910e-3f);
    p = fmaf(p, f, 5.55041087e-2f);
    p = fmaf(p, f, 2.40226507e-1f);
    p = fmaf(p, f, 6.93147180e-1f);
    p = fmaf(p, f, 1.0f);
    return p * __int_as_float(((int)fl + 127) << 23);
}
static __device__ __forceinline__ uint32_t sw_off(int row, int chunk) {
    return (uint32_t)(row * 64 + ((chunk ^ ((row >> 1) & 3)) << 4));
}
#define CPA16(dst, src) \
    asm volatile("cp.async.cg.shared.global [%0], [%1], 16;" :: "r"(dst), "l"(src))
#define CPCOMMIT asm volatile("cp.async.commit_group;" ::: "memory")
#define CPWAIT2  asm volatile("cp.async.wait_group 2;" ::: "memory")
#define CPWAIT0  asm volatile("cp.async.wait_group 0;" ::: "memory")

// ===========================================================================
// prep_all: all fp32 -> fp16 conversions in one kernel.
// regions (pair indices): [0,2097152) x->gXh(hi only)
//   [2097152,3145728) wq -> gW[0:] hi+lo
//   [3145728,4194304) wk -> gW[1048576:] hi+lo
//   [4194304,4718592) wv -> gW[2097152:] hi+lo
//   [4718592,5242880) wo -> gWo hi+lo
// ===========================================================================
__global__ void prep_all(const float* __restrict__ x,
                         const float* __restrict__ wq,
                         const float* __restrict__ wk,
                         const float* __restrict__ wv,
                         const float* __restrict__ wo)
{
    int i = blockIdx.x * blockDim.x + threadIdx.x;
    int stride = gridDim.x * blockDim.x;
    for (; i < 5242880; i += stride) {
        if (i < 2097152) {
            float2 v = *(const float2*)(x + 2 * (size_t)i);
            gXh[i] = pack2h(v.x, v.y);
        } else {
            const float* src; uint32_t* dh; uint32_t* dl; int j;
            if (i < 3145728)      { j = i - 2097152; src = wq; dh = gWh;           dl = gWl; }
            else if (i < 4194304) { j = i - 3145728; src = wk; dh = gWh + 1048576; dl = gWl + 1048576; }
            else if (i < 4718592) { j = i - 4194304; src = wv; dh = gWh + 2097152; dl = gWl + 2097152; }
            else                  { j = i - 4718592; src = wo; dh = gWoh;          dl = gWol; }
            float2 v = *(const float2*)(src + 2 * (size_t)j);
            uint32_t h, l;
            splitpair(v.x, v.y, h, l);
            dh[j] = h; dl[j] = l;
        }
    }
}

// prep_ctx: gAh = fp16(gCtx * scale + bias)  (hi only)
__global__ void prep_ctx()
{
    int i = blockIdx.x * blockDim.x + threadIdx.x;
    int stride = gridDim.x * blockDim.x;
    for (; i < 2097152; i += stride) {
        int m = i >> 9, kp = i & 511, b = m >> 10;
        float2 v  = *(const float2*)&gCtx[(size_t)m * 1024 + 2 * kp];
        float2 sc = *(const float2*)&gScaleArr[b * 1024 + 2 * kp];
        float2 bi = *(const float2*)&gBiasArr [b * 1024 + 2 * kp];
        gAh[i] = pack2h(v.x * sc.x + bi.x, v.y * sc.y + bi.y);
    }
}

// ===========================================================================
// mma_gemm<MODE>: fp16 2-pass GEMM, 128x128 tile, BK=32,
// 4-stage circular cp.async pipeline, one __syncthreads per chunk.
// smem: 4 buffers x (Ah 8K | Bh 8K | Bl 8K) = 96KB dynamic.
// ===========================================================================
template<int MODE>
__global__ __launch_bounds__(256, 2)
void mma_gemm(const float* __restrict__ wqb, const float* __restrict__ wkb,
              const float* __restrict__ wvb, const float* __restrict__ ob,
              float* __restrict__ out)
{
    extern __shared__ char sm[];
    const uint32_t smb = smem_u32(sm);
    const int tid  = threadIdx.x;
    const int lane = tid & 31;
    const int warp = tid >> 5;
    const int wm   = warp >> 1;
    const int wn   = warp & 1;
    const int n0 = blockIdx.x * 128;
    const int m0 = blockIdx.y * 128;
    const int b  = m0 >> 10;

    const uint32_t* Ah = (MODE == 0) ? gXh : gAh;
    const uint32_t* Bh = (MODE == 0) ? gWh : gWoh;
    const uint32_t* Bl = (MODE == 0) ? gWl : gWol;
    const float* Wb;
    if (MODE == 0) {
        if (n0 < 2048)      Wb = wqb + n0;
        else if (n0 < 4096) Wb = wkb + (n0 - 2048);
        else                Wb = wvb + (n0 - 4096);
    } else {
        Wb = ob + n0;
    }

    float acc[2][8][4];
#pragma unroll
    for (int i = 0; i < 2; i++)
#pragma unroll
        for (int j = 0; j < 8; j++)
#pragma unroll
            for (int v = 0; v < 4; v++) acc[i][j][v] = 0.f;

    // stage chunk c into buffer buf: 3 tiles (Ah, Bh, Bl), 1536 x 16B
#define STAGE_GEMM(c, buf)                                                        \
    {                                                                             \
        _Pragma("unroll")                                                         \
        for (int i = 0; i < 6; i++) {                                             \
            int t = tid + i * 256;                                                \
            int tile = t >> 9;                                                    \
            int r = (t >> 2) & 127;                                               \
            int u = t & 3;                                                        \
            uint32_t dst = smb + (uint32_t)(buf) * 24576u + tile * 8192u          \
                           + sw_off(r, u);                                        \
            const uint32_t* sa = (tile == 0) ? Ah : (tile == 1) ? Bh : Bl;        \
            const uint32_t* src = sa + (size_t)((tile == 0 ? m0 : n0) + r) * 512  \
                                   + (c) * 16 + u * 4;                            \
            CPA16(dst, src);                                                      \
        }                                                                         \
        CPCOMMIT;                                                                 \
    }

    STAGE_GEMM(0, 0);
    STAGE_GEMM(1, 1);
    STAGE_GEMM(2, 2);
    for (int c = 0; c < 32; c++) {
        if (c < 29) { CPWAIT2; } else { CPWAIT0; }
        __syncthreads();
        if (c < 29) STAGE_GEMM(c + 3, (c + 3) & 3);

        const uint32_t base = smb + (uint32_t)(c & 3) * 24576u;
        const uint32_t AhU = base;
        const uint32_t BhiU = base + 8192u, BloU = base + 16384u;
#pragma unroll
        for (int kk = 0; kk < 2; kk++) {
            uint32_t ah[2][4];
            const int arow = wm * 32 + (lane & 7) + (((lane >> 3) & 1) << 3);
            const int achunk = kk * 2 + (lane >> 4);
#pragma unroll
            for (int mi = 0; mi < 2; mi++)
                ldm_x4(ah[mi], AhU + sw_off(arow + mi * 16, achunk));
            const int brow0 = wn * 64 + (lane & 7) + ((lane >> 4) << 3);
            const int bchunk = kk * 2 + ((lane >> 3) & 1);
#pragma unroll
            for (int half = 0; half < 2; half++) {
                uint32_t bhf[2][4], blf[2][4];
#pragma unroll
                for (int j = 0; j < 2; j++) {
                    uint32_t off = sw_off(brow0 + half * 32 + j * 16, bchunk);
                    ldm_x4(bhf[j], BhiU + off);
                    ldm_x4(blf[j], BloU + off);
                }
#pragma unroll
                for (int mi = 0; mi < 2; mi++)
#pragma unroll
                    for (int j = 0; j < 2; j++)
#pragma unroll
                        for (int s = 0; s < 2; s++) {
                            float* cp = acc[mi][half * 4 + j * 2 + s];
                            mma16816(cp, ah[mi], &bhf[j][s * 2]);
                            mma16816(cp, ah[mi], &blf[j][s * 2]);
                        }
            }
        }
    }
#undef STAGE_GEMM

    if (MODE == 0) {
        const int sect = n0 >> 10;
        uint32_t* dstH = (sect == 0) ? gQ1h : (sect == 1) ? gQ2h :
                         (sect == 2) ? gK1h : (sect == 3) ? gK2h : gVh;
        uint32_t* dstL = (sect == 2) ? gK1l : (sect == 3) ? gK2l :
                         (sect == 4) ? gVl : nullptr;
        const bool dual = (sect >= 2);
#pragma unroll
        for (int mi = 0; mi < 2; mi++) {
            int m = m0 + wm * 32 + mi * 16 + (lane >> 2);
            int s = m & 1023;
#pragma unroll
            for (int nh = 0; nh < 8; nh++) {
                int nl = wn * 64 + nh * 8 + 2 * (lane & 3);
                int nn = (n0 & 1023) + nl;
                int h = nn >> 6, dh = nn & 63;
                float b0 = Wb[nl], b1 = Wb[nl + 1];
                size_t base = ((size_t)((b << 4) + h) * 1024 + s) * 32 + (dh >> 1);
                if (dual) {
                    uint32_t h0, l0, h1, l1;
                    splitpair(acc[mi][nh][0] + b0, acc[mi][nh][1] + b1, h0, l0);
                    splitpair(acc[mi][nh][2] + b0, acc[mi][nh][3] + b1, h1, l1);
                    dstH[base] = h0; dstL[base] = l0;
                    dstH[base + 256] = h1; dstL[base + 256] = l1;
                } else {
                    dstH[base]       = pack2h(acc[mi][nh][0] + b0, acc[mi][nh][1] + b1);
                    dstH[base + 256] = pack2h(acc[mi][nh][2] + b0, acc[mi][nh][3] + b1);
                }
            }
        }
    } else {
#pragma unroll
        for (int mi = 0; mi < 2; mi++) {
            int m = m0 + wm * 32 + mi * 16 + (lane >> 2);
#pragma unroll
            for (int nh = 0; nh < 8; nh++) {
                int nl = wn * 64 + nh * 8 + 2 * (lane & 3);
                float b0 = Wb[nl], b1 = Wb[nl + 1];
                float2 v0; v0.x = acc[mi][nh][0] + b0; v0.y = acc[mi][nh][1] + b1;
                float2 v1; v1.x = acc[mi][nh][2] + b0; v1.y = acc[mi][nh][3] + b1;
                *(float2*)&out[(size_t)m * 1024 + n0 + nl]       = v0;
                *(float2*)&out[(size_t)(m + 8) * 1024 + n0 + nl] = v1;
            }
        }
    }
}

// ===========================================================================
// attn_kernel: variant-sequential, fp16 2-pass, ~103KB smem -> 2 CTAs/SM.
// smem: S fp32[16][1032] (66048) | KV stage 2x16KB (32768) | Pc 2x2KB (4096)
// ===========================================================================
#define SD 1032
#define OFF_KV 66048u
#define OFF_PC 98816u
#define ATTN_SMEM 102912

// stage 64 keys (hi+lo) of a packed [bh][1024][32-u32] tensor into buf
static __device__ __forceinline__ void stage64(uint32_t smb, const uint32_t* sH,
                                               const uint32_t* sL, int bh,
                                               int ch64, int buf, int tid)
{
#pragma unroll
    for (int i = 0; i < 4; i++) {
        int t = tid + i * 256;            // 0..1023
        int tile = t >> 9;                // 0 = hi, 1 = lo
        int row = (t >> 3) & 63;
        int cu = t & 7;
        uint32_t dst = smb + OFF_KV + buf * 16384u + tile * 8192u +
                       row * 128u + (uint32_t)((cu ^ (row & 7)) << 4);
        const uint32_t* src = (tile ? sL : sH) +
                              ((size_t)bh * 1024 + ch64 * 64 + row) * 32 + cu * 4;
        CPA16(dst, src);
    }
    CPCOMMIT;
}

__global__ __launch_bounds__(256, 2)
void attn_kernel(const float* __restrict__ Cmask,
                 const int*   __restrict__ pad,
                 const float* __restrict__ lamp,
                 float* __restrict__ attn1,
                 float* __restrict__ attn2)
{
    extern __shared__ char smc[];
    const uint32_t smb = smem_u32(smc);
    float* S = (float*)smc;

    const int qt = blockIdx.x;
    const int h  = blockIdx.y;
    const int b  = blockIdx.z;
    const int tid  = threadIdx.x;
    const int wid  = tid >> 5;
    const int lane = tid & 31;
    const int bh = b * 16 + h;
    const int qbase = qt * 16;
    const int r  = lane >> 2;
    const int c2 = (lane & 3) * 2;
    const int* padrow = pad + b * 1024;

    // ---------------- score pass (one variant), Q hi-only, 2-pass ----------
#define SCORE_PASS(KH, KL, QH)                                                   \
    {                                                                            \
        uint32_t qh[4][4];                                                       \
        {                                                                        \
            size_t qb0 = ((size_t)bh * 1024 + qbase + r) * 32;                   \
            size_t qb1 = qb0 + 8 * 32;                                           \
            _Pragma("unroll")                                                    \
            for (int kk = 0; kk < 4; kk++) {                                     \
                int p = kk * 8 + (lane & 3);                                     \
                qh[kk][0] = QH[qb0 + p];                                         \
                qh[kk][1] = QH[qb1 + p];                                         \
                qh[kk][2] = QH[qb0 + p + 4];                                     \
                qh[kk][3] = QH[qb1 + p + 4];                                     \
            }                                                                    \
        }                                                                        \
        for (int ch = 0; ch < 16; ch++) {                                        \
            CPWAIT0;                                                             \
            __syncthreads();                                                     \
            if (ch < 15) stage64(smb, KH, KL, bh, ch + 1, (ch + 1) & 1, tid);    \
            const uint32_t KVhiU = smb + OFF_KV + (ch & 1) * 16384u;             \
            const uint32_t KVloU = KVhiU + 8192u;                                \
            float c0[4] = {0.f, 0.f, 0.f, 0.f};                                  \
            const int brow = wid * 8 + (lane & 7);                               \
            _Pragma("unroll")                                                    \
            for (int kk = 0; kk < 4; kk++) {                                     \
                int bch = kk * 2 + ((lane >> 3) & 1);                            \
                uint32_t off = brow * 128 + ((bch ^ (brow & 7)) << 4);           \
                uint32_t bhf[2], blf[2];                                         \
                ldm_x2(bhf, KVhiU + off);                                        \
                ldm_x2(blf, KVloU + off);                                        \
                mma16816(c0, qh[kk], bhf);                                       \
                mma16816(c0, qh[kk], blf);                                       \
            }                                                                    \
            const int col = ch * 64 + wid * 8 + c2;                              \
            float2 v;                                                            \
            v.x = c0[0] * 0.125f; v.y = c0[1] * 0.125f;                          \
            *(float2*)&S[r * SD + col] = v;                                      \
            v.x = c0[2] * 0.125f; v.y = c0[3] * 0.125f;                          \
            *(float2*)&S[(r + 8) * SD + col] = v;                                \
        }                                                                        \
    }

    // ---------------- variant 2 scores -> softmax -> attn2 ----------------
    stage64(smb, gK2h, gK2l, bh, 0, 0, tid);
    SCORE_PASS(gK2h, gK2l, gQ2h);

    // prefetch K1 chunk 0 during softmax
    stage64(smb, gK1h, gK1l, bh, 0, 0, tid);
    __syncthreads();

    for (int q = wid; q < 16; q += 8) {
        float* row = S + q * SD;
        float vreg[32];
        float m = -3.4e38f;
#pragma unroll
        for (int j = 0; j < 32; j++) {
            int k = lane + 32 * j;
            float v = row[k];
            if (padrow[k] == 0) v = -1e9f;
            vreg[j] = v;
            m = fmaxf(m, v);
        }
#pragma unroll
        for (int o = 16; o > 0; o >>= 1) m = fmaxf(m, __shfl_xor_sync(0xffffffffu, m, o));
        float s = 0.f;
#pragma unroll
        for (int j = 0; j < 32; j++) { vreg[j] = fexp(vreg[j] - m); s += vreg[j]; }
#pragma unroll
        for (int o = 16; o > 0; o >>= 1) s += __shfl_xor_sync(0xffffffffu, s, o);
        float rr = 1.0f / s;
        float* gout = attn2 + ((size_t)bh * 1024 + qbase + q) * 1024;
#pragma unroll
        for (int j = 0; j < 32; j++)
            gout[lane + 32 * j] = vreg[j] * rr;
    }
    __syncthreads();

    // ---------------- variant 1 scores -> softmax+combine -> attn1 & P in S -
    SCORE_PASS(gK1h, gK1l, gQ1h);

    // prefetch V chunk 0 during softmax
    stage64(smb, gVh, gVl, bh, 0, 0, tid);
    __syncthreads();

    {
        const float lam = lamp[0];
        for (int q = wid; q < 16; q += 8) {
            float* row = S + q * SD;
            float vreg[32];
            float m = -3.4e38f;
#pragma unroll
            for (int j = 0; j < 32; j++) {
                int k = lane + 32 * j;
                float v = row[k];
                if (padrow[k] == 0) v = -1e9f;
                vreg[j] = v;
                m = fmaxf(m, v);
            }
#pragma unroll
            for (int o = 16; o > 0; o >>= 1) m = fmaxf(m, __shfl_xor_sync(0xffffffffu, m, o));
            float s = 0.f;
#pragma unroll
            for (int j = 0; j < 32; j++) { vreg[j] = fexp(vreg[j] - m); s += vreg[j]; }
#pragma unroll
            for (int o = 16; o > 0; o >>= 1) s += __shfl_xor_sync(0xffffffffu, s, o);
            float rr = 1.0f / s;
            float* gout = attn1 + ((size_t)bh * 1024 + qbase + q) * 1024;
            const float* a2g = attn2 + ((size_t)bh * 1024 + qbase + q) * 1024;
            const float* cg  = Cmask + ((size_t)b * 1024 + qbase + q) * 1024;
#pragma unroll
            for (int j = 0; j < 32; j++) {
                int k = lane + 32 * j;
                float e = vreg[j] * rr;
                gout[k] = e;
                row[k] = cg[k] * (e - lam * a2g[k]);
            }
        }
    }
    __syncthreads();

    // ---------------- phase 2: ctx = P @ V, P hi-only, 2-pass --------------
    {
        const uint32_t ua = (uint32_t)((((lane & 15) * 2 +
                             ((lane >> 4) ^ (((lane & 15) >> 2) & 1)))) << 4);
        float cacc[4] = {0.f, 0.f, 0.f, 0.f};
        for (int ch = 0; ch < 16; ch++) {
            const int buf = ch & 1;
            // pack P chunk (16q x 64k) fp16 hi into Pc[buf]
            {
                uint32_t* Pchi = (uint32_t*)(smc + OFF_PC + buf * 2048u);
#pragma unroll
                for (int i = 0; i < 2; i++) {
                    int pidx = tid + i * 256;          // 0..511
                    int q  = pidx >> 5;
                    int kp = pidx & 31;
                    int kl = kp * 2;
                    uint32_t hv = pack2h(S[q * SD + ch * 64 + kl],
                                         S[q * SD + ch * 64 + kl + 1]);
                    int kb16  = kl >> 4;
                    int colin = kl & 15;
                    int half  = colin >> 3;
                    int w     = (colin & 7) >> 1;
                    int u     = q * 2 + (half ^ ((q >> 2) & 1));
                    Pchi[kb16 * 128 + u * 4 + w] = hv;
                }
            }
            CPWAIT0;
            __syncthreads();
            if (ch < 15) stage64(smb, gVh, gVl, bh, ch + 1, buf ^ 1, tid);

            const uint32_t VhiU = smb + OFF_KV + buf * 16384u;
            const uint32_t VloU = VhiU + 8192u;
            const uint32_t PbU  = smb + OFF_PC + buf * 2048u;
#pragma unroll
            for (int k2 = 0; k2 < 2; k2++) {
                int lrow = k2 * 32 + (lane >> 3) * 8 + (lane & 7);
                uint32_t boff = lrow * 128 + ((wid ^ (lrow & 7)) << 4);
                uint32_t bhf[4], blf[4];
                ldm_x4_t(bhf, VhiU + boff);
                ldm_x4_t(blf, VloU + boff);
#pragma unroll
                for (int sub = 0; sub < 2; sub++) {
                    int kb16 = k2 * 2 + sub;
                    uint32_t ah[4];
                    ldm_x4(ah, PbU + kb16 * 512 + ua);
                    mma16816(cacc, ah, &bhf[sub * 2]);
                    mma16816(cacc, ah, &blf[sub * 2]);
                }
            }
            __syncthreads();
        }
        size_t base = ((size_t)(b * 1024 + qbase + r)) * 1024 + h * 64 + wid * 8 + c2;
        float2 v0; v0.x = cacc[0]; v0.y = cacc[1];
        float2 v1; v1.x = cacc[2]; v1.y = cacc[3];
        *(float2*)&gCtx[base]            = v0;
        *(float2*)&gCtx[base + 8 * 1024] = v1;
    }
#undef SCORE_PASS
}

// ---------------------------------------------------------------------------
// stats_kernel: GroupNorm stats -> folded per-(b,d) scale/bias
// ---------------------------------------------------------------------------
__global__ void stats_kernel(const float* __restrict__ gnw,
                             const float* __restrict__ gnb)
{
    const int bh = blockIdx.x;
    const int b = bh >> 4, h = bh & 15;
    const int tid = threadIdx.x;
    __shared__ float rs[256], rq[256];
    float s = 0.f, sq = 0.f;
    for (int t = tid; t < 65536; t += 256) {
        int srow = t >> 6, d = t & 63;
        float x = gCtx[((size_t)b * 1024 + srow) * 1024 + h * 64 + d];
        s += x; sq += x * x;
    }
    rs[tid] = s; rq[tid] = sq;
    __syncthreads();
    for (int o = 128; o > 0; o >>= 1) {
        if (tid < o) { rs[tid] += rs[tid + o]; rq[tid] += rq[tid + o]; }
        __syncthreads();
    }
    if (tid < 64) {
        float mean = rs[0] * (1.0f / 65536.0f);
        float var  = rq[0] * (1.0f / 65536.0f) - mean * mean;
        float rstd = rsqrtf(var + 1e-5f);
        int d = h * 64 + tid;
        float w = gnw[d];
        float scl = rstd * w * 0.19999999999999996f;
        gScaleArr[b * 1024 + d] = scl;
        gBiasArr [b * 1024 + d] = (gnb[d] - mean * rstd * w) * 0.19999999999999996f;
    }
}

// ---------------------------------------------------------------------------
// Launch
// ---------------------------------------------------------------------------
extern "C" void kernel_launch(void* const* d_in, const int* in_sizes, int n_in,
                              void* d_out, int out_size)
{
    const float* x    = (const float*)d_in[0];
    const float* lam  = (const float*)d_in[1];
    const float* C    = (const float*)d_in[2];
    const int*   pad  = (const int*)  d_in[3];
    const float* wq   = (const float*)d_in[4];
    const float* wqb  = (const float*)d_in[5];
    const float* wk   = (const float*)d_in[6];
    const float* wkb  = (const float*)d_in[7];
    const float* wv   = (const float*)d_in[8];
    const float* wvb  = (const float*)d_in[9];
    const float* wo   = (const float*)d_in[10];
    const float* wob  = (const float*)d_in[11];
    const float* gnw  = (const float*)d_in[12];
    const float* gnb  = (const float*)d_in[13];

    float* out   = (float*)d_out;
    float* attn1 = out + (size_t)BB * SS * DD;
    float* attn2 = attn1 + (size_t)BB * HH * SS * SS;

    cudaFuncSetAttribute(attn_kernel, cudaFuncAttributeMaxDynamicSharedMemorySize,
                         ATTN_SMEM);
    cudaFuncSetAttribute(mma_gemm<0>, cudaFuncAttributeMaxDynamicSharedMemorySize, 98304);
    cudaFuncSetAttribute(mma_gemm<1>, cudaFuncAttributeMaxDynamicSharedMemorySize, 98304);

    prep_all<<<512, 256>>>(x, wq, wk, wv, wo);
    mma_gemm<0><<<dim3(40, 32), 256, 98304>>>(wqb, wkb, wvb, nullptr, nullptr);
    attn_kernel<<<dim3(64, 16, 4), 256, ATTN_SMEM>>>(C, pad, lam, attn1, attn2);
    stats_kernel<<<64, 256>>>(gnw, gnb);
    prep_ctx<<<512, 256>>>();
    mma_gemm<1><<<dim3(8, 32), 256, 98304>>>(nullptr, nullptr, nullptr, wob, out);
}